// round 2
// baseline (speedup 1.0000x reference)
#include <cuda_runtime.h>
#include <math.h>

#define T_STEPS 256
#define B_SZ 64
#define H_SZ 1024
#define H4 4096
#define O_SZ 10000
#define TB (T_STEPS * B_SZ)

// ---------------- scratch (device globals; no allocations allowed) ----------
__device__ float g_Wc[(size_t)H_SZ * H4];        // W_proj @ W_x      (16 MB)
__device__ float g_bc[H4];                        // b_proj@W_x + b_lstm
__device__ float g_px[(size_t)TB * H4];           // precomputed input gates (256 MB)
__device__ float g_res[(size_t)TB * H_SZ];        // h_t for all t     (64 MB)
__device__ float g_c[B_SZ * H_SZ];                // cell state

// ---------------- bc[n] = sum_k b_proj[k] * W_x[k,n] + b_lstm[n] ------------
__global__ void bc_kernel(const float* __restrict__ b_proj,
                          const float* __restrict__ W_x,
                          const float* __restrict__ b_lstm,
                          float* __restrict__ bc)
{
    int n = blockIdx.x * blockDim.x + threadIdx.x;
    if (n >= H4) return;
    float s = b_lstm[n];
    for (int k = 0; k < H_SZ; k++)
        s += b_proj[k] * W_x[(size_t)k * H4 + n];
    bc[n] = s;
}

// ---------------- generic SGEMM: C[M,N] = A[M,K] @ B[K,N] (+bias) -----------
// A optionally row-gathered via gidx (embedding lookup fused into GEMM).
// 128x128 block tile, K-tile 8, 256 threads, 8x8 per-thread micro-tile.
// Requires M % 128 == 0, K % 8 == 0. N arbitrary (guarded).
template <bool GATHER>
__global__ __launch_bounds__(256, 2)
void sgemm_kernel(const float* __restrict__ A, const float* __restrict__ Bm,
                  const int* __restrict__ gidx, const float* __restrict__ bias,
                  float* __restrict__ C, int M, int N, int K)
{
    __shared__ float As[8][128];
    __shared__ float Bs[8][128];

    const int bm = blockIdx.y * 128;
    const int bn = blockIdx.x * 128;
    const int tid = threadIdx.x;

    const int a_row = tid >> 1;          // 0..127
    const int a_kc  = (tid & 1) * 4;     // 0 or 4
    const int b_kr  = tid >> 5;          // 0..7
    const int b_nc  = (tid & 31) * 4;    // 0..124

    const float* Arow;
    {
        int r = bm + a_row;
        size_t ar = GATHER ? (size_t)gidx[r] : (size_t)r;
        Arow = A + ar * (size_t)K;
    }

    const int tx = tid & 15;
    const int ty = tid >> 4;

    float acc[8][8];
#pragma unroll
    for (int i = 0; i < 8; i++)
#pragma unroll
        for (int j = 0; j < 8; j++) acc[i][j] = 0.f;

    for (int k0 = 0; k0 < K; k0 += 8) {
        // A tile (transposed store)
        float4 av = *(const float4*)(Arow + k0 + a_kc);
        As[a_kc + 0][a_row] = av.x;
        As[a_kc + 1][a_row] = av.y;
        As[a_kc + 2][a_row] = av.z;
        As[a_kc + 3][a_row] = av.w;

        // B tile (N-guarded)
        int gn = bn + b_nc;
        const float* bptr = Bm + (size_t)(k0 + b_kr) * N + gn;
        float4 bv;
        if (gn + 3 < N) {
            bv = *(const float4*)bptr;
        } else {
            bv.x = (gn + 0 < N) ? bptr[0] : 0.f;
            bv.y = (gn + 1 < N) ? bptr[1] : 0.f;
            bv.z = (gn + 2 < N) ? bptr[2] : 0.f;
            bv.w = (gn + 3 < N) ? bptr[3] : 0.f;
        }
        *(float4*)&Bs[b_kr][b_nc] = bv;

        __syncthreads();
#pragma unroll
        for (int kk = 0; kk < 8; kk++) {
            float4 a0 = *(const float4*)&As[kk][ty * 4];
            float4 a1 = *(const float4*)&As[kk][64 + ty * 4];
            float4 b0 = *(const float4*)&Bs[kk][tx * 4];
            float4 b1 = *(const float4*)&Bs[kk][64 + tx * 4];
            float ar[8] = {a0.x, a0.y, a0.z, a0.w, a1.x, a1.y, a1.z, a1.w};
            float br[8] = {b0.x, b0.y, b0.z, b0.w, b1.x, b1.y, b1.z, b1.w};
#pragma unroll
            for (int i = 0; i < 8; i++)
#pragma unroll
                for (int j = 0; j < 8; j++) acc[i][j] += ar[i] * br[j];
        }
        __syncthreads();
    }

#pragma unroll
    for (int i = 0; i < 8; i++) {
        int r = bm + ((i < 4) ? (ty * 4 + i) : (64 + ty * 4 + i - 4));
#pragma unroll
        for (int j = 0; j < 8; j++) {
            int cidx = bn + ((j < 4) ? (tx * 4 + j) : (64 + tx * 4 + j - 4));
            if (cidx < N) {
                float v = acc[i][j];
                if (bias) v += bias[cidx];
                C[(size_t)r * N + cidx] = v;
            }
        }
    }
}

// ---------------- fused LSTM step: gates = px_t + h @ W_h, then pointwise ---
// Grid: 128 blocks, each owns 8 hidden units (all 4 gates) x all 64 batch rows.
// 128 threads: thread = (unit u in 0..7) x (4 batch rows). Reads h from
// res[t-1] (or input h at t=0), writes h_new into res[t] and c in-place.
__global__ __launch_bounds__(128)
void lstm_step_kernel(const float* __restrict__ px_t,   // [B, 4H]
                      const float* __restrict__ W_h,    // [H, 4H]
                      const float* __restrict__ h_in,   // [B, H]
                      float* __restrict__ res_t,        // [B, H]
                      float* __restrict__ hf_out,
                      float* __restrict__ cf_out,
                      int last)
{
    __shared__ float Hs[16][64];   // [k][b]
    __shared__ float Ws[16][32];   // [k][u*4+g]

    const int tid = threadIdx.x;
    const int u0  = blockIdx.x * 8;
    const int u   = tid & 7;
    const int b0  = (tid >> 3) * 4;   // 0..60

    float acc[4][4];
#pragma unroll
    for (int r = 0; r < 4; r++)
#pragma unroll
        for (int g = 0; g < 4; g++) acc[r][g] = 0.f;

    for (int k0 = 0; k0 < H_SZ; k0 += 16) {
        // load h tile: 64 rows x 16 k  (2 float4 per thread)
#pragma unroll
        for (int q = 0; q < 2; q++) {
            int idx4 = q * 128 + tid;          // 0..255
            int row  = idx4 >> 2;              // 0..63
            int kc   = (idx4 & 3) * 4;         // 0,4,8,12
            float4 hv = *(const float4*)(h_in + (size_t)row * H_SZ + k0 + kc);
            Hs[kc + 0][row] = hv.x;
            Hs[kc + 1][row] = hv.y;
            Hs[kc + 2][row] = hv.z;
            Hs[kc + 3][row] = hv.w;
        }
        // load W_h tile: 16 k x (8 units x 4 gates)  (4 scalars per thread)
#pragma unroll
        for (int p = 0; p < 4; p++) {
            int idx = p * 128 + tid;           // 0..511
            int uu  = idx & 7;
            int gg  = (idx >> 3) & 3;
            int kk  = idx >> 5;                // 0..15
            Ws[kk][uu * 4 + gg] =
                W_h[(size_t)(k0 + kk) * H4 + gg * H_SZ + u0 + uu];
        }
        __syncthreads();
#pragma unroll
        for (int kk = 0; kk < 16; kk++) {
            float4 wv = *(const float4*)&Ws[kk][u * 4];
            float h0 = Hs[kk][b0 + 0];
            float h1 = Hs[kk][b0 + 1];
            float h2 = Hs[kk][b0 + 2];
            float h3 = Hs[kk][b0 + 3];
            acc[0][0] += h0 * wv.x; acc[0][1] += h0 * wv.y; acc[0][2] += h0 * wv.z; acc[0][3] += h0 * wv.w;
            acc[1][0] += h1 * wv.x; acc[1][1] += h1 * wv.y; acc[1][2] += h1 * wv.z; acc[1][3] += h1 * wv.w;
            acc[2][0] += h2 * wv.x; acc[2][1] += h2 * wv.y; acc[2][2] += h2 * wv.z; acc[2][3] += h2 * wv.w;
            acc[3][0] += h3 * wv.x; acc[3][1] += h3 * wv.y; acc[3][2] += h3 * wv.z; acc[3][3] += h3 * wv.w;
        }
        __syncthreads();
    }

    const int ug = u0 + u;
#pragma unroll
    for (int r = 0; r < 4; r++) {
        int b = b0 + r;
        const float* pxb = px_t + (size_t)b * H4;
        float gi = acc[r][0] + pxb[0 * H_SZ + ug];
        float gf = acc[r][1] + pxb[1 * H_SZ + ug];
        float gg = acc[r][2] + pxb[2 * H_SZ + ug];
        float go = acc[r][3] + pxb[3 * H_SZ + ug];
        float si = 1.f / (1.f + expf(-gi));
        float sf = 1.f / (1.f + expf(-gf));
        float so = 1.f / (1.f + expf(-go));
        float tg = tanhf(gg);
        int ci = b * H_SZ + ug;
        float cn = sf * g_c[ci] + si * tg;
        float hn = so * tanhf(cn);
        g_c[ci]   = cn;
        res_t[ci] = hn;
        if (last) { hf_out[ci] = hn; cf_out[ci] = cn; }
    }
}

// ---------------- launch --------------------------------------------------
extern "C" void kernel_launch(void* const* d_in, const int* in_sizes, int n_in,
                              void* d_out, int out_size)
{
    const int*   x      = (const int*)  d_in[0];
    const float* h      = (const float*)d_in[1];
    const float* c      = (const float*)d_in[2];
    const float* emb    = (const float*)d_in[3];
    const float* W_proj = (const float*)d_in[4];
    const float* b_proj = (const float*)d_in[5];
    const float* W_x    = (const float*)d_in[6];
    const float* W_h    = (const float*)d_in[7];
    const float* b_lstm = (const float*)d_in[8];
    const float* W_out  = (const float*)d_in[9];
    const float* b_out  = (const float*)d_in[10];
    float* out = (float*)d_out;

    float *Wc, *bc, *px, *res, *cbuf;
    cudaGetSymbolAddress((void**)&Wc,   g_Wc);
    cudaGetSymbolAddress((void**)&bc,   g_bc);
    cudaGetSymbolAddress((void**)&px,   g_px);
    cudaGetSymbolAddress((void**)&res,  g_res);
    cudaGetSymbolAddress((void**)&cbuf, g_c);

    // cell state init (async D2D copy: graph-capturable)
    cudaMemcpyAsync(cbuf, c, (size_t)B_SZ * H_SZ * sizeof(float),
                    cudaMemcpyDeviceToDevice, 0);

    // combined bias: bc = b_proj @ W_x + b_lstm
    bc_kernel<<<(H4 + 255) / 256, 256>>>(b_proj, W_x, b_lstm, bc);

    // Wc = W_proj @ W_x   [H, 4H]
    sgemm_kernel<false><<<dim3(H4 / 128, H_SZ / 128), 256>>>(
        W_proj, W_x, nullptr, nullptr, Wc, H_SZ, H4, H_SZ);

    // px = emb[x] @ Wc + bc   [T*B, 4H]  (embedding gather fused)
    sgemm_kernel<true><<<dim3(H4 / 128, TB / 128), 256>>>(
        emb, Wc, x, bc, px, TB, H4, H_SZ);

    // sequential LSTM scan; res[t] doubles as next step's h input
    float* hf_out = out + (size_t)TB * O_SZ;
    float* cf_out = hf_out + (size_t)B_SZ * H_SZ;
    for (int t = 0; t < T_STEPS; t++) {
        const float* h_in = (t == 0) ? h : (res + (size_t)(t - 1) * B_SZ * H_SZ);
        lstm_step_kernel<<<H_SZ / 8, 128>>>(
            px + (size_t)t * B_SZ * H4, W_h, h_in,
            res + (size_t)t * B_SZ * H_SZ,
            hf_out, cf_out, (t == T_STEPS - 1) ? 1 : 0);
    }

    // output = res @ W_out + b_out   [T*B, O]
    sgemm_kernel<false><<<dim3((O_SZ + 127) / 128, TB / 128), 256>>>(
        res, W_out, nullptr, b_out, out, TB, O_SZ, H_SZ);
}

// round 4
// speedup vs baseline: 2.3248x; 2.3248x over previous
#include <cuda_runtime.h>
#include <cuda_bf16.h>
#include <cstdint>
#include <math.h>

#define T_STEPS 256
#define B_SZ 64
#define H_SZ 1024
#define H4 4096
#define O_SZ 10000
#define TB (T_STEPS * B_SZ)
#define BH (B_SZ * H_SZ)

// ===================== low-level helpers (sm_80+ features only) =============
__device__ __forceinline__ uint32_t smem_u32(const void* p) {
    uint32_t a;
    asm("{ .reg .u64 t; cvta.to.shared.u64 t, %1; cvt.u32.u64 %0, t; }"
        : "=r"(a) : "l"(p));
    return a;
}
__device__ __forceinline__ void ldsm4(uint32_t* r, uint32_t a) {
    asm volatile("ldmatrix.sync.aligned.m8n8.x4.shared.b16 {%0,%1,%2,%3}, [%4];"
                 : "=r"(r[0]), "=r"(r[1]), "=r"(r[2]), "=r"(r[3]) : "r"(a));
}
__device__ __forceinline__ void mma_bf16(float* c, const uint32_t* a,
                                         uint32_t b0, uint32_t b1) {
    asm volatile(
        "mma.sync.aligned.m16n8k16.row.col.f32.bf16.bf16.f32 "
        "{%0,%1,%2,%3}, {%4,%5,%6,%7}, {%8,%9}, {%0,%1,%2,%3};"
        : "+f"(c[0]), "+f"(c[1]), "+f"(c[2]), "+f"(c[3])
        : "r"(a[0]), "r"(a[1]), "r"(a[2]), "r"(a[3]), "r"(b0), "r"(b1));
}
__device__ __forceinline__ void cp8(uint32_t dst, const void* src, uint32_t sz) {
    asm volatile("cp.async.ca.shared.global [%0], [%1], 8, %2;"
                 :: "r"(dst), "l"(src), "r"(sz) : "memory");
}
#define CP_COMMIT() asm volatile("cp.async.commit_group;" ::: "memory")
#define CP_WAIT1()  asm volatile("cp.async.wait_group 1;" ::: "memory")

__device__ __forceinline__ void split_val(float x, __nv_bfloat16& hi, __nv_bfloat16& lo) {
    hi = __float2bfloat16(x);
    lo = __float2bfloat16(x - __bfloat162float(hi));
}

// ===================== scratch (device globals) ==============================
__device__ float          g_px[(size_t)TB * H4];
__device__ float          g_c[BH];
__device__ float          g_bc[H4];
__device__ __nv_bfloat16  g_res_hi[(size_t)(T_STEPS + 1) * BH];
__device__ __nv_bfloat16  g_res_lo[(size_t)(T_STEPS + 1) * BH];
__device__ __nv_bfloat16  g_emb_hi[(size_t)O_SZ * H_SZ], g_emb_lo[(size_t)O_SZ * H_SZ];
__device__ __nv_bfloat16  g_WxT_hi[(size_t)H4 * H_SZ],   g_WxT_lo[(size_t)H4 * H_SZ];
__device__ __nv_bfloat16  g_WhT_hi[(size_t)H4 * H_SZ],   g_WhT_lo[(size_t)H4 * H_SZ];
__device__ __nv_bfloat16  g_WoT_hi[(size_t)O_SZ * H_SZ], g_WoT_lo[(size_t)O_SZ * H_SZ];
__device__ __nv_bfloat16  g_Wp_hi[(size_t)H_SZ * H_SZ],  g_Wp_lo[(size_t)H_SZ * H_SZ];
__device__ __nv_bfloat16  g_WcT_hi[(size_t)H4 * H_SZ],   g_WcT_lo[(size_t)H4 * H_SZ];

// ===================== pre-pass kernels ======================================
__global__ void split_kernel(const float* __restrict__ in,
                             __nv_bfloat16* __restrict__ hi,
                             __nv_bfloat16* __restrict__ lo, long n) {
    long i = (long)blockIdx.x * blockDim.x + threadIdx.x;
    long stride = (long)gridDim.x * blockDim.x;
    for (; i < n; i += stride) split_val(in[i], hi[i], lo[i]);
}

__global__ void transpose_split_kernel(const float* __restrict__ in,
                                       __nv_bfloat16* __restrict__ hiT,
                                       __nv_bfloat16* __restrict__ loT,
                                       int R, int C) {
    __shared__ float ts[32][33];
    int c0 = blockIdx.x * 32, r0 = blockIdx.y * 32;
    int tx = threadIdx.x & 31, ty = threadIdx.x >> 5;
    for (int rr = ty; rr < 32; rr += 8) {
        int r = r0 + rr, c = c0 + tx;
        ts[rr][tx] = (r < R && c < C) ? in[(size_t)r * C + c] : 0.f;
    }
    __syncthreads();
    for (int cc = ty; cc < 32; cc += 8) {
        int c = c0 + cc, r = r0 + tx;
        if (c < C && r < R) {
            __nv_bfloat16 h, l;
            split_val(ts[tx][cc], h, l);
            hiT[(size_t)c * R + r] = h;
            loT[(size_t)c * R + r] = l;
        }
    }
}

__global__ void bc_kernel(const float* __restrict__ b_proj,
                          const float* __restrict__ W_x,
                          const float* __restrict__ b_lstm,
                          float* __restrict__ bc) {
    int n = blockIdx.x * blockDim.x + threadIdx.x;
    if (n >= H4) return;
    float s = b_lstm[n];
    for (int k = 0; k < H_SZ; k++) s += b_proj[k] * W_x[(size_t)k * H4 + n];
    bc[n] = s;
}

// ===================== big GEMM via mma.sync (bf16x3 ~ fp32) =================
// C[M,N] = A[M,1024] @ B[N,1024]^T.  Block tile 128x128, k-tile 32,
// 8 warps (2x4), warp tile 64x32, cp.async double buffer.
// SMEM stage layout (bytes): Ah 0, Al 10240, Bh 20480, Bl 30720; stage 40960.
#define G_SMEM_BYTES (2 * 40960)

template <bool GATHER, bool SPLIT_OUT>
__global__ __launch_bounds__(256, 1)
void mma_gemm(const __nv_bfloat16* __restrict__ Ah, const __nv_bfloat16* __restrict__ Al,
              const __nv_bfloat16* __restrict__ Bh, const __nv_bfloat16* __restrict__ Bl,
              const int* __restrict__ gidx, const float* __restrict__ bias,
              float* __restrict__ C,
              __nv_bfloat16* __restrict__ Ch, __nv_bfloat16* __restrict__ Cl,
              int M, int N)
{
    extern __shared__ __align__(16) char smem[];
    const uint32_t sb = smem_u32(smem);
    const int tid = threadIdx.x, lane = tid & 31, wid = tid >> 5;
    const int bm = blockIdx.y * 128, bn = blockIdx.x * 128;
    const int wm = (wid >> 2) * 64, wn = (wid & 3) * 32;

    // per-thread cp.async descriptors (A: 4 segs, B: 4 segs of 4 bf16)
    long a_off[4], b_off[4];
    uint32_t a_s[4], b_sz[4];
#pragma unroll
    for (int i = 0; i < 4; i++) {
        int seg = i * 256 + tid;
        int r = seg >> 3, c4 = (seg & 7) * 4;
        long ar = GATHER ? (long)gidx[bm + r] : (long)(bm + r);
        a_off[i] = ar * H_SZ + c4;
        a_s[i] = (uint32_t)(r * 80 + c4 * 2);
        int gn = bn + r;
        b_sz[i]  = (gn < N) ? 8u : 0u;
        b_off[i] = (long)((gn < N) ? gn : 0) * H_SZ + c4;
    }

    float acc[4][4][4];
#pragma unroll
    for (int m = 0; m < 4; m++)
#pragma unroll
        for (int j = 0; j < 4; j++)
#pragma unroll
            for (int q = 0; q < 4; q++) acc[m][j][q] = 0.f;

#define G_LOAD(ck, s) do {                                                    \
    const long ko = (long)(ck) * 32;                                          \
    const uint32_t st = sb + (s) * 40960;                                     \
    _Pragma("unroll")                                                         \
    for (int i = 0; i < 4; i++) {                                             \
        cp8(st + a_s[i],         Ah + a_off[i] + ko, 8u);                     \
        cp8(st + 10240 + a_s[i], Al + a_off[i] + ko, 8u);                     \
        cp8(st + 20480 + a_s[i], Bh + b_off[i] + ko, b_sz[i]);                \
        cp8(st + 30720 + a_s[i], Bl + b_off[i] + ko, b_sz[i]);                \
    }                                                                         \
} while (0)

    G_LOAD(0, 0); CP_COMMIT();
    G_LOAD(1, 1); CP_COMMIT();

    for (int ck = 0; ck < 32; ck++) {
        const int s = ck & 1;
        CP_WAIT1();
        __syncthreads();
        const uint32_t sA = sb + s * 40960;
        const uint32_t sB = sA + 20480;
#pragma unroll
        for (int ks = 0; ks < 2; ks++) {
            uint32_t ah[4][4], al[4][4], bh[8], bl[8];
            const int arow = lane & 15;
            const uint32_t ac = (uint32_t)(((lane >> 4) * 8 + ks * 16) * 2);
#pragma unroll
            for (int mf = 0; mf < 4; mf++) {
                uint32_t ad = sA + (uint32_t)((wm + mf * 16 + arow) * 80) + ac;
                ldsm4(ah[mf], ad);
                ldsm4(al[mf], ad + 10240);
            }
            const int brow = (lane & 7) + ((lane >> 4) & 1) * 8;
            const uint32_t bc = (uint32_t)(((((lane >> 3) & 1) * 8) + ks * 16) * 2);
#pragma unroll
            for (int pf = 0; pf < 2; pf++) {
                uint32_t bd = sB + (uint32_t)((wn + pf * 16 + brow) * 80) + bc;
                ldsm4(&bh[pf * 4], bd);
                ldsm4(&bl[pf * 4], bd + 10240);
            }
#pragma unroll
            for (int m = 0; m < 4; m++)
#pragma unroll
                for (int j = 0; j < 4; j++) {
                    const int bi = (j >> 1) * 4 + (j & 1) * 2;
                    mma_bf16(acc[m][j], ah[m], bh[bi], bh[bi + 1]);
                    mma_bf16(acc[m][j], al[m], bh[bi], bh[bi + 1]);
                    mma_bf16(acc[m][j], ah[m], bl[bi], bl[bi + 1]);
                }
        }
        __syncthreads();
        if (ck + 2 < 32) G_LOAD(ck + 2, s);
        CP_COMMIT();
    }

    // epilogue: direct global stores
#pragma unroll
    for (int m = 0; m < 4; m++) {
        const int r0 = bm + wm + m * 16 + (lane >> 2);
#pragma unroll
        for (int j = 0; j < 4; j++) {
            const int col = bn + wn + j * 8 + (lane & 3) * 2;
#pragma unroll
            for (int hh = 0; hh < 2; hh++) {
                const int r = r0 + hh * 8;
                const float v0 = acc[m][j][hh * 2 + 0];
                const float v1 = acc[m][j][hh * 2 + 1];
                if (SPLIT_OUT) {
                    __nv_bfloat16 vh, vl;
                    if (col < N) {
                        split_val(v0, vh, vl);
                        Ch[(size_t)r * N + col] = vh; Cl[(size_t)r * N + col] = vl;
                    }
                    if (col + 1 < N) {
                        split_val(v1, vh, vl);
                        Ch[(size_t)r * N + col + 1] = vh; Cl[(size_t)r * N + col + 1] = vl;
                    }
                } else {
                    if (col < N)     C[(size_t)r * N + col]     = v0 + bias[col];
                    if (col + 1 < N) C[(size_t)r * N + col + 1] = v1 + bias[col + 1];
                }
            }
        }
    }
#undef G_LOAD
}

// ===================== fused LSTM step via mma.sync ==========================
// CTA = 8 hidden units (all 4 gates) x 64 batch. M=32 rows (m = g*8+u), N=64,
// K=1024. 4 warps (2x2), warp tile 16x32. Then fused pointwise + bf16 split.
// SMEM stage (bytes): Ah 0, Al 2560, Bh 5120, Bl 10240; stage 15360, 2 stages.
__global__ __launch_bounds__(128, 1)
void lstm_step_mma(const __nv_bfloat16* __restrict__ WhTh,
                   const __nv_bfloat16* __restrict__ WhTl,
                   const __nv_bfloat16* __restrict__ hh,
                   const __nv_bfloat16* __restrict__ hl,
                   const float* __restrict__ px_t,
                   __nv_bfloat16* __restrict__ outh,
                   __nv_bfloat16* __restrict__ outl,
                   float* __restrict__ hf, float* __restrict__ cf, int last)
{
    __shared__ __align__(16) char smem[30720];
    const uint32_t sb = smem_u32(smem);
    const int tid = threadIdx.x, lane = tid & 31, wid = tid >> 5;
    const int u0 = blockIdx.x * 8;
    const int wm = (wid >> 1) * 16, wn = (wid & 1) * 32;

    long a_off[2]; uint32_t a_s[2];
#pragma unroll
    for (int i = 0; i < 2; i++) {
        int seg = i * 128 + tid;
        int r = seg >> 3, c4 = (seg & 7) * 4;     // r: 0..31
        long grow = (long)(r >> 3) * H_SZ + u0 + (r & 7);   // gate*1024 + unit
        a_off[i] = grow * H_SZ + c4;
        a_s[i] = (uint32_t)(r * 80 + c4 * 2);
    }
    long b_off[4]; uint32_t b_s[4];
#pragma unroll
    for (int i = 0; i < 4; i++) {
        int seg = i * 128 + tid;
        int r = seg >> 3, c4 = (seg & 7) * 4;     // r: 0..63 (batch)
        b_off[i] = (long)r * H_SZ + c4;
        b_s[i] = (uint32_t)(r * 80 + c4 * 2);
    }

    float acc[4][4];
#pragma unroll
    for (int j = 0; j < 4; j++)
#pragma unroll
        for (int q = 0; q < 4; q++) acc[j][q] = 0.f;

#define S_LOAD(ck, s) do {                                                    \
    const long ko = (long)(ck) * 32;                                          \
    const uint32_t st = sb + (s) * 15360;                                     \
    _Pragma("unroll")                                                         \
    for (int i = 0; i < 2; i++) {                                             \
        cp8(st + a_s[i],        WhTh + a_off[i] + ko, 8u);                    \
        cp8(st + 2560 + a_s[i], WhTl + a_off[i] + ko, 8u);                    \
    }                                                                         \
    _Pragma("unroll")                                                         \
    for (int i = 0; i < 4; i++) {                                             \
        cp8(st + 5120 + b_s[i],  hh + b_off[i] + ko, 8u);                     \
        cp8(st + 10240 + b_s[i], hl + b_off[i] + ko, 8u);                     \
    }                                                                         \
} while (0)

    S_LOAD(0, 0); CP_COMMIT();
    S_LOAD(1, 1); CP_COMMIT();

    for (int ck = 0; ck < 32; ck++) {
        const int s = ck & 1;
        CP_WAIT1();
        __syncthreads();
        const uint32_t sA = sb + s * 15360;
        const uint32_t sB = sA + 5120;
#pragma unroll
        for (int ks = 0; ks < 2; ks++) {
            uint32_t ah[4], al[4], bh[8], bl[8];
            const uint32_t ac = (uint32_t)(((lane >> 4) * 8 + ks * 16) * 2);
            {
                uint32_t ad = sA + (uint32_t)((wm + (lane & 15)) * 80) + ac;
                ldsm4(ah, ad);
                ldsm4(al, ad + 2560);
            }
            const int brow = (lane & 7) + ((lane >> 4) & 1) * 8;
            const uint32_t bc = (uint32_t)(((((lane >> 3) & 1) * 8) + ks * 16) * 2);
#pragma unroll
            for (int pf = 0; pf < 2; pf++) {
                uint32_t bd = sB + (uint32_t)((wn + pf * 16 + brow) * 80) + bc;
                ldsm4(&bh[pf * 4], bd);
                ldsm4(&bl[pf * 4], bd + 5120);
            }
#pragma unroll
            for (int j = 0; j < 4; j++) {
                const int bi = (j >> 1) * 4 + (j & 1) * 2;
                mma_bf16(acc[j], ah, bh[bi], bh[bi + 1]);
                mma_bf16(acc[j], al, bh[bi], bh[bi + 1]);
                mma_bf16(acc[j], ah, bl[bi], bl[bi + 1]);
            }
        }
        __syncthreads();
        if (ck + 2 < 32) S_LOAD(ck + 2, s);
        CP_COMMIT();
    }

    __syncthreads();   // all warps done reading stages before Gs overlay
    float* Gs = (float*)smem;   // [32][65] fp32 gate exchange
    {
        const int row = wm + (lane >> 2);
#pragma unroll
        for (int j = 0; j < 4; j++) {
            const int col = wn + j * 8 + (lane & 3) * 2;
            Gs[row * 65 + col]           = acc[j][0];
            Gs[row * 65 + col + 1]       = acc[j][1];
            Gs[(row + 8) * 65 + col]     = acc[j][2];
            Gs[(row + 8) * 65 + col + 1] = acc[j][3];
        }
    }
    __syncthreads();

    {
        const int u = tid & 7;
        const int b0 = (tid >> 3) * 4;
        const int gu = u0 + u;
#pragma unroll
        for (int jj = 0; jj < 4; jj++) {
            const int b = b0 + jj;
            const float* pxb = px_t + (size_t)b * H4;
            float gi = Gs[(0 * 8 + u) * 65 + b] + pxb[gu];
            float gf = Gs[(1 * 8 + u) * 65 + b] + pxb[1024 + gu];
            float gg = Gs[(2 * 8 + u) * 65 + b] + pxb[2048 + gu];
            float go = Gs[(3 * 8 + u) * 65 + b] + pxb[3072 + gu];
            float si = 1.f / (1.f + expf(-gi));
            float sf = 1.f / (1.f + expf(-gf));
            float so = 1.f / (1.f + expf(-go));
            float tg = tanhf(gg);
            const int ci = b * H_SZ + gu;
            float cn = sf * g_c[ci] + si * tg;
            float hn = so * tanhf(cn);
            g_c[ci] = cn;
            __nv_bfloat16 vh, vl;
            split_val(hn, vh, vl);
            outh[ci] = vh; outl[ci] = vl;
            if (last) { hf[ci] = hn; cf[ci] = cn; }
        }
    }
#undef S_LOAD
}

// ===================== launch ================================================
extern "C" void kernel_launch(void* const* d_in, const int* in_sizes, int n_in,
                              void* d_out, int out_size)
{
    const int*   x      = (const int*)  d_in[0];
    const float* h      = (const float*)d_in[1];
    const float* c      = (const float*)d_in[2];
    const float* emb    = (const float*)d_in[3];
    const float* W_proj = (const float*)d_in[4];
    const float* b_proj = (const float*)d_in[5];
    const float* W_x    = (const float*)d_in[6];
    const float* W_h    = (const float*)d_in[7];
    const float* b_lstm = (const float*)d_in[8];
    const float* W_out  = (const float*)d_in[9];
    const float* b_out  = (const float*)d_in[10];
    float* out = (float*)d_out;

    float *px, *cbuf, *bc;
    __nv_bfloat16 *resh, *resl, *embh, *embl, *wxth, *wxtl, *whth, *whtl;
    __nv_bfloat16 *woth, *wotl, *wph, *wpl, *wcth, *wctl;
    cudaGetSymbolAddress((void**)&px,   g_px);
    cudaGetSymbolAddress((void**)&cbuf, g_c);
    cudaGetSymbolAddress((void**)&bc,   g_bc);
    cudaGetSymbolAddress((void**)&resh, g_res_hi);
    cudaGetSymbolAddress((void**)&resl, g_res_lo);
    cudaGetSymbolAddress((void**)&embh, g_emb_hi);
    cudaGetSymbolAddress((void**)&embl, g_emb_lo);
    cudaGetSymbolAddress((void**)&wxth, g_WxT_hi);
    cudaGetSymbolAddress((void**)&wxtl, g_WxT_lo);
    cudaGetSymbolAddress((void**)&whth, g_WhT_hi);
    cudaGetSymbolAddress((void**)&whtl, g_WhT_lo);
    cudaGetSymbolAddress((void**)&woth, g_WoT_hi);
    cudaGetSymbolAddress((void**)&wotl, g_WoT_lo);
    cudaGetSymbolAddress((void**)&wph,  g_Wp_hi);
    cudaGetSymbolAddress((void**)&wpl,  g_Wp_lo);
    cudaGetSymbolAddress((void**)&wcth, g_WcT_hi);
    cudaGetSymbolAddress((void**)&wctl, g_WcT_lo);

    cudaFuncSetAttribute(mma_gemm<false, false>,
                         cudaFuncAttributeMaxDynamicSharedMemorySize, G_SMEM_BYTES);
    cudaFuncSetAttribute(mma_gemm<true, false>,
                         cudaFuncAttributeMaxDynamicSharedMemorySize, G_SMEM_BYTES);
    cudaFuncSetAttribute(mma_gemm<false, true>,
                         cudaFuncAttributeMaxDynamicSharedMemorySize, G_SMEM_BYTES);

    cudaMemcpyAsync(cbuf, c, (size_t)BH * sizeof(float),
                    cudaMemcpyDeviceToDevice, 0);

    // pre-pass
    split_kernel<<<512, 256>>>(W_proj, wph, wpl, (long)H_SZ * H_SZ);
    split_kernel<<<2048, 256>>>(emb, embh, embl, (long)O_SZ * H_SZ);
    split_kernel<<<64, 256>>>(h, resh, resl, (long)BH);   // slot 0 = h_{-1}
    transpose_split_kernel<<<dim3(H4 / 32, H_SZ / 32), 256>>>(W_x, wxth, wxtl, H_SZ, H4);
    transpose_split_kernel<<<dim3(H4 / 32, H_SZ / 32), 256>>>(W_h, whth, whtl, H_SZ, H4);
    transpose_split_kernel<<<dim3((O_SZ + 31) / 32, H_SZ / 32), 256>>>(W_out, woth, wotl, H_SZ, O_SZ);
    bc_kernel<<<(H4 + 255) / 256, 256>>>(b_proj, W_x, b_lstm, bc);

    // WcT[j,k] = sum_m W_x[m,j] * W_proj[k,m]  -> bf16 hi/lo
    mma_gemm<false, true><<<dim3(H_SZ / 128, H4 / 128), 256, G_SMEM_BYTES>>>(
        wxth, wxtl, wph, wpl, nullptr, nullptr, nullptr, wcth, wctl, H4, H_SZ);

    // px = emb[x] @ WcT^T + bc   [TB, 4H] fp32
    mma_gemm<true, false><<<dim3(H4 / 128, TB / 128), 256, G_SMEM_BYTES>>>(
        embh, embl, wcth, wctl, x, bc, px, nullptr, nullptr, TB, H4);

    // sequential LSTM scan (bf16 hi/lo h ping-pong through res slabs)
    float* hf_out = out + (size_t)TB * O_SZ;
    float* cf_out = hf_out + BH;
    for (int t = 0; t < T_STEPS; t++) {
        lstm_step_mma<<<128, 128>>>(
            whth, whtl,
            resh + (size_t)t * BH, resl + (size_t)t * BH,
            px + (size_t)t * B_SZ * H4,
            resh + (size_t)(t + 1) * BH, resl + (size_t)(t + 1) * BH,
            hf_out, cf_out, (t == T_STEPS - 1) ? 1 : 0);
    }

    // out = res @ W_out^T + b_out   [TB, O] fp32
    mma_gemm<false, false><<<dim3((O_SZ + 127) / 128, TB / 128), 256, G_SMEM_BYTES>>>(
        resh + BH, resl + BH, woth, wotl, nullptr, b_out, out, nullptr, nullptr,
        TB, O_SZ);
}

// round 5
// speedup vs baseline: 2.6224x; 1.1280x over previous
#include <cuda_runtime.h>
#include <cuda_bf16.h>
#include <cuda_fp16.h>
#include <cstdint>
#include <math.h>

#define T_STEPS 256
#define B_SZ 64
#define H_SZ 1024
#define H4 4096
#define O_SZ 10000
#define TB (T_STEPS * B_SZ)
#define BH (B_SZ * H_SZ)

// ===================== low-level helpers (sm_80+ features only) =============
__device__ __forceinline__ uint32_t smem_u32(const void* p) {
    uint32_t a;
    asm("{ .reg .u64 t; cvta.to.shared.u64 t, %1; cvt.u32.u64 %0, t; }"
        : "=r"(a) : "l"(p));
    return a;
}
__device__ __forceinline__ void ldsm4(uint32_t* r, uint32_t a) {
    asm volatile("ldmatrix.sync.aligned.m8n8.x4.shared.b16 {%0,%1,%2,%3}, [%4];"
                 : "=r"(r[0]), "=r"(r[1]), "=r"(r[2]), "=r"(r[3]) : "r"(a));
}
__device__ __forceinline__ void mma_bf16(float* c, const uint32_t* a,
                                         uint32_t b0, uint32_t b1) {
    asm volatile(
        "mma.sync.aligned.m16n8k16.row.col.f32.bf16.bf16.f32 "
        "{%0,%1,%2,%3}, {%4,%5,%6,%7}, {%8,%9}, {%0,%1,%2,%3};"
        : "+f"(c[0]), "+f"(c[1]), "+f"(c[2]), "+f"(c[3])
        : "r"(a[0]), "r"(a[1]), "r"(a[2]), "r"(a[3]), "r"(b0), "r"(b1));
}
__device__ __forceinline__ void mma_f16(float* c, const uint32_t* a,
                                        uint32_t b0, uint32_t b1) {
    asm volatile(
        "mma.sync.aligned.m16n8k16.row.col.f32.f16.f16.f32 "
        "{%0,%1,%2,%3}, {%4,%5,%6,%7}, {%8,%9}, {%0,%1,%2,%3};"
        : "+f"(c[0]), "+f"(c[1]), "+f"(c[2]), "+f"(c[3])
        : "r"(a[0]), "r"(a[1]), "r"(a[2]), "r"(a[3]), "r"(b0), "r"(b1));
}
__device__ __forceinline__ void cp16(uint32_t dst, const void* src, uint32_t sz) {
    asm volatile("cp.async.cg.shared.global [%0], [%1], 16, %2;"
                 :: "r"(dst), "l"(src), "r"(sz) : "memory");
}
#define CP_COMMIT() asm volatile("cp.async.commit_group;" ::: "memory")
#define CP_WAIT1()  asm volatile("cp.async.wait_group 1;" ::: "memory")

__device__ __forceinline__ void split_bf(float x, __nv_bfloat16& hi, __nv_bfloat16& lo) {
    hi = __float2bfloat16(x);
    lo = __float2bfloat16(x - __bfloat162float(hi));
}
__device__ __forceinline__ void split_h16(float x, __half& hi, __half& lo) {
    hi = __float2half(x);
    lo = __float2half(x - __half2float(hi));
}

// ===================== scratch (device globals) ==============================
__device__ float          g_px[(size_t)TB * H4];
__device__ float          g_c[BH];
__device__ float          g_bc[H4];
__device__ __nv_bfloat16  g_res_hi[(size_t)(T_STEPS + 1) * BH];
__device__ __nv_bfloat16  g_res_lo[(size_t)(T_STEPS + 1) * BH];
__device__ __half         g_res16h[(size_t)T_STEPS * BH];
__device__ __half         g_res16l[(size_t)T_STEPS * BH];
__device__ __half         g_emb16h[(size_t)O_SZ * H_SZ], g_emb16l[(size_t)O_SZ * H_SZ];
__device__ __nv_bfloat16  g_WxT_hi[(size_t)H4 * H_SZ],   g_WxT_lo[(size_t)H4 * H_SZ];
__device__ __nv_bfloat16  g_WhT_hi[(size_t)H4 * H_SZ],   g_WhT_lo[(size_t)H4 * H_SZ];
__device__ __half         g_WoT16[(size_t)O_SZ * H_SZ];
__device__ __nv_bfloat16  g_Wp_hi[(size_t)H_SZ * H_SZ],  g_Wp_lo[(size_t)H_SZ * H_SZ];
__device__ __half         g_WcT16[(size_t)H4 * H_SZ];

// ===================== pre-pass kernels ======================================
__global__ void split_kernel(const float* __restrict__ in,
                             __nv_bfloat16* __restrict__ hi,
                             __nv_bfloat16* __restrict__ lo, long n) {
    long i = (long)blockIdx.x * blockDim.x + threadIdx.x;
    long stride = (long)gridDim.x * blockDim.x;
    for (; i < n; i += stride) split_bf(in[i], hi[i], lo[i]);
}
__global__ void split16_kernel(const float* __restrict__ in,
                               __half* __restrict__ hi,
                               __half* __restrict__ lo, long n) {
    long i = (long)blockIdx.x * blockDim.x + threadIdx.x;
    long stride = (long)gridDim.x * blockDim.x;
    for (; i < n; i += stride) split_h16(in[i], hi[i], lo[i]);
}
// [R x C] fp32 -> [C x R] bf16 hi/lo
__global__ void transpose_split_kernel(const float* __restrict__ in,
                                       __nv_bfloat16* __restrict__ hiT,
                                       __nv_bfloat16* __restrict__ loT,
                                       int R, int C) {
    __shared__ float ts[32][33];
    int c0 = blockIdx.x * 32, r0 = blockIdx.y * 32;
    int tx = threadIdx.x & 31, ty = threadIdx.x >> 5;
    for (int rr = ty; rr < 32; rr += 8) {
        int r = r0 + rr, c = c0 + tx;
        ts[rr][tx] = (r < R && c < C) ? in[(size_t)r * C + c] : 0.f;
    }
    __syncthreads();
    for (int cc = ty; cc < 32; cc += 8) {
        int c = c0 + cc, r = r0 + tx;
        if (c < C && r < R) {
            __nv_bfloat16 h, l;
            split_bf(ts[tx][cc], h, l);
            hiT[(size_t)c * R + r] = h;
            loT[(size_t)c * R + r] = l;
        }
    }
}
// [R x C] fp32 -> [C x R] fp16 (single)
__global__ void transpose16_kernel(const float* __restrict__ in,
                                   __half* __restrict__ hiT, int R, int C) {
    __shared__ float ts[32][33];
    int c0 = blockIdx.x * 32, r0 = blockIdx.y * 32;
    int tx = threadIdx.x & 31, ty = threadIdx.x >> 5;
    for (int rr = ty; rr < 32; rr += 8) {
        int r = r0 + rr, c = c0 + tx;
        ts[rr][tx] = (r < R && c < C) ? in[(size_t)r * C + c] : 0.f;
    }
    __syncthreads();
    for (int cc = ty; cc < 32; cc += 8) {
        int c = c0 + cc, r = r0 + tx;
        if (c < C && r < R) hiT[(size_t)c * R + r] = __float2half(ts[tx][cc]);
    }
}
__global__ void bc_kernel(const float* __restrict__ b_proj,
                          const float* __restrict__ W_x,
                          const float* __restrict__ b_lstm,
                          float* __restrict__ bc) {
    int n = blockIdx.x * blockDim.x + threadIdx.x;
    if (n >= H4) return;
    float s = b_lstm[n];
    for (int k = 0; k < H_SZ; k++) s += b_proj[k] * W_x[(size_t)k * H4 + n];
    bc[n] = s;
}

// ===================== bf16x3 GEMM (128x128) — used only for Wc ============
// C[M,N] = A[M,1024] @ B[N,1024]^T, output written as fp16 single.
// SMEM stage: Ah 0, Al 10240, Bh 20480, Bl 30720; stage 40960, 2 stages.
#define G_SMEM_BYTES (2 * 40960)
__global__ __launch_bounds__(256, 1)
void mma_gemm_bf16(const __nv_bfloat16* __restrict__ Ah, const __nv_bfloat16* __restrict__ Al,
                   const __nv_bfloat16* __restrict__ Bh, const __nv_bfloat16* __restrict__ Bl,
                   __half* __restrict__ C16, int M, int N)
{
    extern __shared__ __align__(16) char smem[];
    const uint32_t sb = smem_u32(smem);
    const int tid = threadIdx.x, lane = tid & 31, wid = tid >> 5;
    const int bm = blockIdx.y * 128, bn = blockIdx.x * 128;
    const int wm = (wid >> 2) * 64, wn = (wid & 3) * 32;

    // 16B cp.async: A hi/lo 512 ops each, B hi/lo 512 each -> 8/thread
    long a_off[2], b_off[2];
    uint32_t a_s[2], b_s[2], b_sz[2];
#pragma unroll
    for (int q = 0; q < 2; q++) {
        int pos = q * 256 + tid;
        int r = pos >> 2, c8 = (pos & 3) * 8;
        a_off[q] = (long)(bm + r) * H_SZ + c8;
        a_s[q] = (uint32_t)(r * 80 + (pos & 3) * 16);
        int gn = bn + r;
        b_sz[q]  = (gn < N) ? 16u : 0u;
        b_off[q] = (long)((gn < N) ? gn : 0) * H_SZ + c8;
        b_s[q] = a_s[q];
    }

    float acc[4][4][4];
#pragma unroll
    for (int m = 0; m < 4; m++)
#pragma unroll
        for (int j = 0; j < 4; j++)
#pragma unroll
            for (int q = 0; q < 4; q++) acc[m][j][q] = 0.f;

#define GB_LOAD(ck, s) do {                                                   \
    const long ko = (long)(ck) * 32;                                          \
    const uint32_t st = sb + (s) * 40960;                                     \
    _Pragma("unroll")                                                         \
    for (int q = 0; q < 2; q++) {                                             \
        cp16(st + a_s[q],         Ah + a_off[q] + ko, 16u);                   \
        cp16(st + 10240 + a_s[q], Al + a_off[q] + ko, 16u);                   \
        cp16(st + 20480 + b_s[q], Bh + b_off[q] + ko, b_sz[q]);               \
        cp16(st + 30720 + b_s[q], Bl + b_off[q] + ko, b_sz[q]);               \
    }                                                                         \
} while (0)

    GB_LOAD(0, 0); CP_COMMIT();
    GB_LOAD(1, 1); CP_COMMIT();

    for (int ck = 0; ck < 32; ck++) {
        const int s = ck & 1;
        CP_WAIT1();
        __syncthreads();
        const uint32_t sA = sb + s * 40960;
        const uint32_t sB = sA + 20480;
#pragma unroll
        for (int ks = 0; ks < 2; ks++) {
            uint32_t ah[4][4], al[4][4], bh[8], bl[8];
            const int arow = lane & 15;
            const uint32_t ac = (uint32_t)(((lane >> 4) * 8 + ks * 16) * 2);
#pragma unroll
            for (int mf = 0; mf < 4; mf++) {
                uint32_t ad = sA + (uint32_t)((wm + mf * 16 + arow) * 80) + ac;
                ldsm4(ah[mf], ad);
                ldsm4(al[mf], ad + 10240);
            }
            const int brow = (lane & 7) + ((lane >> 4) & 1) * 8;
            const uint32_t bc = (uint32_t)(((((lane >> 3) & 1) * 8) + ks * 16) * 2);
#pragma unroll
            for (int pf = 0; pf < 2; pf++) {
                uint32_t bd = sB + (uint32_t)((wn + pf * 16 + brow) * 80) + bc;
                ldsm4(&bh[pf * 4], bd);
                ldsm4(&bl[pf * 4], bd + 10240);
            }
#pragma unroll
            for (int m = 0; m < 4; m++)
#pragma unroll
                for (int j = 0; j < 4; j++) {
                    const int bi = (j >> 1) * 4 + (j & 1) * 2;
                    mma_bf16(acc[m][j], ah[m], bh[bi], bh[bi + 1]);
                    mma_bf16(acc[m][j], al[m], bh[bi], bh[bi + 1]);
                    mma_bf16(acc[m][j], ah[m], bl[bi], bl[bi + 1]);
                }
        }
        __syncthreads();
        if (ck + 2 < 32) GB_LOAD(ck + 2, s);
        CP_COMMIT();
    }

#pragma unroll
    for (int m = 0; m < 4; m++) {
        const int r0 = bm + wm + m * 16 + (lane >> 2);
#pragma unroll
        for (int j = 0; j < 4; j++) {
            const int col = bn + wn + j * 8 + (lane & 3) * 2;
#pragma unroll
            for (int hh = 0; hh < 2; hh++) {
                const int r = r0 + hh * 8;
                if (col < N)     C16[(size_t)r * N + col]     = __float2half(acc[m][j][hh * 2 + 0]);
                if (col + 1 < N) C16[(size_t)r * N + col + 1] = __float2half(acc[m][j][hh * 2 + 1]);
            }
        }
    }
#undef GB_LOAD
}

// ===================== fp16x2 GEMM (128x256) — px and out ===================
// C[M,N] = (Ah+Al)[M,1024] @ Bh[N,1024]^T + bias.  8 warps 2x4, warp 64x64.
// SMEM stage: Ah 0, Al 10240, B 20480; stage 40960, 2 stages (80KB).
#define G2_SMEM_BYTES (2 * 40960)
template <bool GATHER>
__global__ __launch_bounds__(256, 1)
void mma_gemm_f16(const __half* __restrict__ Ah, const __half* __restrict__ Al,
                  const __half* __restrict__ Bh,
                  const int* __restrict__ gidx, const float* __restrict__ bias,
                  float* __restrict__ C, int M, int N)
{
    extern __shared__ __align__(16) char smem[];
    const uint32_t sb = smem_u32(smem);
    const int tid = threadIdx.x, lane = tid & 31, wid = tid >> 5;
    const int bm = blockIdx.y * 128, bn = blockIdx.x * 256;
    const int wm = (wid >> 2) * 64, wn = (wid & 3) * 64;

    // A: 512 16B-ops (2/thread); B: 1024 16B-ops (4/thread)
    long a_off[2];
    uint32_t a_s[2];
#pragma unroll
    for (int q = 0; q < 2; q++) {
        int pos = q * 256 + tid;
        int r = pos >> 2, c8 = (pos & 3) * 8;
        long ar = GATHER ? (long)gidx[bm + r] : (long)(bm + r);
        a_off[q] = ar * H_SZ + c8;
        a_s[q] = (uint32_t)(r * 80 + (pos & 3) * 16);
    }
    long b_off[4];
    uint32_t b_s[4], b_sz[4];
#pragma unroll
    for (int q = 0; q < 4; q++) {
        int pos = q * 256 + tid;
        int r = pos >> 2, c8 = (pos & 3) * 8;
        int gn = bn + r;
        b_sz[q]  = (gn < N) ? 16u : 0u;
        b_off[q] = (long)((gn < N) ? gn : 0) * H_SZ + c8;
        b_s[q] = (uint32_t)(r * 80 + (pos & 3) * 16);
    }

    float acc[4][8][4];
#pragma unroll
    for (int m = 0; m < 4; m++)
#pragma unroll
        for (int j = 0; j < 8; j++)
#pragma unroll
            for (int q = 0; q < 4; q++) acc[m][j][q] = 0.f;

#define G2_LOAD(ck, s) do {                                                   \
    const long ko = (long)(ck) * 32;                                          \
    const uint32_t st = sb + (s) * 40960;                                     \
    _Pragma("unroll")                                                         \
    for (int q = 0; q < 2; q++) {                                             \
        cp16(st + a_s[q],         Ah + a_off[q] + ko, 16u);                   \
        cp16(st + 10240 + a_s[q], Al + a_off[q] + ko, 16u);                   \
    }                                                                         \
    _Pragma("unroll")                                                         \
    for (int q = 0; q < 4; q++)                                               \
        cp16(st + 20480 + b_s[q], Bh + b_off[q] + ko, b_sz[q]);               \
} while (0)

    G2_LOAD(0, 0); CP_COMMIT();
    G2_LOAD(1, 1); CP_COMMIT();

    for (int ck = 0; ck < 32; ck++) {
        const int s = ck & 1;
        CP_WAIT1();
        __syncthreads();
        const uint32_t sA = sb + s * 40960;
        const uint32_t sB = sA + 20480;
#pragma unroll
        for (int ks = 0; ks < 2; ks++) {
            uint32_t ah[4][4], al[4][4], bh[16];
            const int arow = lane & 15;
            const uint32_t ac = (uint32_t)(((lane >> 4) * 8 + ks * 16) * 2);
#pragma unroll
            for (int mf = 0; mf < 4; mf++) {
                uint32_t ad = sA + (uint32_t)((wm + mf * 16 + arow) * 80) + ac;
                ldsm4(ah[mf], ad);
                ldsm4(al[mf], ad + 10240);
            }
            const int brow = (lane & 7) + ((lane >> 4) & 1) * 8;
            const uint32_t bc = (uint32_t)(((((lane >> 3) & 1) * 8) + ks * 16) * 2);
#pragma unroll
            for (int pf = 0; pf < 4; pf++) {
                uint32_t bd = sB + (uint32_t)((wn + pf * 16 + brow) * 80) + bc;
                ldsm4(&bh[pf * 4], bd);
            }
#pragma unroll
            for (int m = 0; m < 4; m++)
#pragma unroll
                for (int j = 0; j < 8; j++) {
                    const int bi = (j >> 1) * 4 + (j & 1) * 2;
                    mma_f16(acc[m][j], ah[m], bh[bi], bh[bi + 1]);
                    mma_f16(acc[m][j], al[m], bh[bi], bh[bi + 1]);
                }
        }
        __syncthreads();
        if (ck + 2 < 32) G2_LOAD(ck + 2, s);
        CP_COMMIT();
    }

#pragma unroll
    for (int m = 0; m < 4; m++) {
        const int r0 = bm + wm + m * 16 + (lane >> 2);
#pragma unroll
        for (int j = 0; j < 8; j++) {
            const int col = bn + wn + j * 8 + (lane & 3) * 2;
#pragma unroll
            for (int hh = 0; hh < 2; hh++) {
                const int r = r0 + hh * 8;
                if (col < N)     C[(size_t)r * N + col]     = acc[m][j][hh * 2 + 0] + bias[col];
                if (col + 1 < N) C[(size_t)r * N + col + 1] = acc[m][j][hh * 2 + 1] + bias[col + 1];
            }
        }
    }
#undef G2_LOAD
}

// ===================== fused LSTM step (bf16x3 mma.sync) =====================
// CTA = 8 units x 4 gates (M=32) x 64 batch, K=1024. 4 warps 2x2, warp 16x32.
// SMEM stage: Ah 0, Al 2560, Bh 5120, Bl 10240; stage 15360, 2 stages.
__global__ __launch_bounds__(128, 1)
void lstm_step_mma(const __nv_bfloat16* __restrict__ WhTh,
                   const __nv_bfloat16* __restrict__ WhTl,
                   const __nv_bfloat16* __restrict__ hh,
                   const __nv_bfloat16* __restrict__ hl,
                   const float* __restrict__ px_t,
                   __nv_bfloat16* __restrict__ outh,
                   __nv_bfloat16* __restrict__ outl,
                   __half* __restrict__ o16h, __half* __restrict__ o16l,
                   float* __restrict__ hf, float* __restrict__ cf, int last)
{
    __shared__ __align__(16) char smem[30720];
    const uint32_t sb = smem_u32(smem);
    const int tid = threadIdx.x, lane = tid & 31, wid = tid >> 5;
    const int u0 = blockIdx.x * 8;
    const int wm = (wid >> 1) * 16, wn = (wid & 1) * 32;

    // A: 128 16B-ops (1/thread); B: 256 16B-ops (2/thread)
    long a_off;
    uint32_t a_s;
    {
        int r = tid >> 2, c8 = (tid & 3) * 8;     // r: 0..31
        long grow = (long)(r >> 3) * H_SZ + u0 + (r & 7);
        a_off = grow * H_SZ + c8;
        a_s = (uint32_t)(r * 80 + (tid & 3) * 16);
    }
    long b_off[2];
    uint32_t b_s[2];
#pragma unroll
    for (int q = 0; q < 2; q++) {
        int pos = q * 128 + tid;
        int r = pos >> 2, c8 = (pos & 3) * 8;     // r: 0..63
        b_off[q] = (long)r * H_SZ + c8;
        b_s[q] = (uint32_t)(r * 80 + (pos & 3) * 16);
    }

    float acc[4][4];
#pragma unroll
    for (int j = 0; j < 4; j++)
#pragma unroll
        for (int q = 0; q < 4; q++) acc[j][q] = 0.f;

#define S_LOAD(ck, s) do {                                                    \
    const long ko = (long)(ck) * 32;                                          \
    const uint32_t st = sb + (s) * 15360;                                     \
    cp16(st + a_s,        WhTh + a_off + ko, 16u);                            \
    cp16(st + 2560 + a_s, WhTl + a_off + ko, 16u);                            \
    _Pragma("unroll")                                                         \
    for (int q = 0; q < 2; q++) {                                             \
        cp16(st + 5120 + b_s[q],  hh + b_off[q] + ko, 16u);                   \
        cp16(st + 10240 + b_s[q], hl + b_off[q] + ko, 16u);                   \
    }                                                                         \
} while (0)

    S_LOAD(0, 0); CP_COMMIT();
    S_LOAD(1, 1); CP_COMMIT();

    for (int ck = 0; ck < 32; ck++) {
        const int s = ck & 1;
        CP_WAIT1();
        __syncthreads();
        const uint32_t sA = sb + s * 15360;
        const uint32_t sB = sA + 5120;
#pragma unroll
        for (int ks = 0; ks < 2; ks++) {
            uint32_t ah[4], al[4], bh[8], bl[8];
            const uint32_t ac = (uint32_t)(((lane >> 4) * 8 + ks * 16) * 2);
            {
                uint32_t ad = sA + (uint32_t)((wm + (lane & 15)) * 80) + ac;
                ldsm4(ah, ad);
                ldsm4(al, ad + 2560);
            }
            const int brow = (lane & 7) + ((lane >> 4) & 1) * 8;
            const uint32_t bc = (uint32_t)(((((lane >> 3) & 1) * 8) + ks * 16) * 2);
#pragma unroll
            for (int pf = 0; pf < 2; pf++) {
                uint32_t bd = sB + (uint32_t)((wn + pf * 16 + brow) * 80) + bc;
                ldsm4(&bh[pf * 4], bd);
                ldsm4(&bl[pf * 4], bd + 5120);
            }
#pragma unroll
            for (int j = 0; j < 4; j++) {
                const int bi = (j >> 1) * 4 + (j & 1) * 2;
                mma_bf16(acc[j], ah, bh[bi], bh[bi + 1]);
                mma_bf16(acc[j], al, bh[bi], bh[bi + 1]);
                mma_bf16(acc[j], ah, bl[bi], bl[bi + 1]);
            }
        }
        __syncthreads();
        if (ck + 2 < 32) S_LOAD(ck + 2, s);
        CP_COMMIT();
    }

    __syncthreads();
    float* Gs = (float*)smem;   // [32][65]
    {
        const int row = wm + (lane >> 2);
#pragma unroll
        for (int j = 0; j < 4; j++) {
            const int col = wn + j * 8 + (lane & 3) * 2;
            Gs[row * 65 + col]           = acc[j][0];
            Gs[row * 65 + col + 1]       = acc[j][1];
            Gs[(row + 8) * 65 + col]     = acc[j][2];
            Gs[(row + 8) * 65 + col + 1] = acc[j][3];
        }
    }
    __syncthreads();

    {
        const int u = tid & 7;
        const int b0 = (tid >> 3) * 4;
        const int gu = u0 + u;
#pragma unroll
        for (int jj = 0; jj < 4; jj++) {
            const int b = b0 + jj;
            const float* pxb = px_t + (size_t)b * H4;
            float gi = Gs[(0 * 8 + u) * 65 + b] + pxb[gu];
            float gf = Gs[(1 * 8 + u) * 65 + b] + pxb[1024 + gu];
            float gg = Gs[(2 * 8 + u) * 65 + b] + pxb[2048 + gu];
            float go = Gs[(3 * 8 + u) * 65 + b] + pxb[3072 + gu];
            float si = 1.f / (1.f + expf(-gi));
            float sf = 1.f / (1.f + expf(-gf));
            float so = 1.f / (1.f + expf(-go));
            float tg = tanhf(gg);
            const int ci = b * H_SZ + gu;
            float cn = sf * g_c[ci] + si * tg;
            float hn = so * tanhf(cn);
            g_c[ci] = cn;
            __nv_bfloat16 vh, vl;
            split_bf(hn, vh, vl);
            outh[ci] = vh; outl[ci] = vl;
            __half fh, fl;
            split_h16(hn, fh, fl);
            o16h[ci] = fh; o16l[ci] = fl;
            if (last) { hf[ci] = hn; cf[ci] = cn; }
        }
    }
#undef S_LOAD
}

// ===================== launch ================================================
extern "C" void kernel_launch(void* const* d_in, const int* in_sizes, int n_in,
                              void* d_out, int out_size)
{
    const int*   x      = (const int*)  d_in[0];
    const float* h      = (const float*)d_in[1];
    const float* c      = (const float*)d_in[2];
    const float* emb    = (const float*)d_in[3];
    const float* W_proj = (const float*)d_in[4];
    const float* b_proj = (const float*)d_in[5];
    const float* W_x    = (const float*)d_in[6];
    const float* W_h    = (const float*)d_in[7];
    const float* b_lstm = (const float*)d_in[8];
    const float* W_out  = (const float*)d_in[9];
    const float* b_out  = (const float*)d_in[10];
    float* out = (float*)d_out;

    float *px, *cbuf, *bc;
    __nv_bfloat16 *resh, *resl, *wxth, *wxtl, *whth, *whtl, *wph, *wpl;
    __half *r16h, *r16l, *e16h, *e16l, *wot16, *wct16;
    cudaGetSymbolAddress((void**)&px,    g_px);
    cudaGetSymbolAddress((void**)&cbuf,  g_c);
    cudaGetSymbolAddress((void**)&bc,    g_bc);
    cudaGetSymbolAddress((void**)&resh,  g_res_hi);
    cudaGetSymbolAddress((void**)&resl,  g_res_lo);
    cudaGetSymbolAddress((void**)&r16h,  g_res16h);
    cudaGetSymbolAddress((void**)&r16l,  g_res16l);
    cudaGetSymbolAddress((void**)&e16h,  g_emb16h);
    cudaGetSymbolAddress((void**)&e16l,  g_emb16l);
    cudaGetSymbolAddress((void**)&wxth,  g_WxT_hi);
    cudaGetSymbolAddress((void**)&wxtl,  g_WxT_lo);
    cudaGetSymbolAddress((void**)&whth,  g_WhT_hi);
    cudaGetSymbolAddress((void**)&whtl,  g_WhT_lo);
    cudaGetSymbolAddress((void**)&wot16, g_WoT16);
    cudaGetSymbolAddress((void**)&wph,   g_Wp_hi);
    cudaGetSymbolAddress((void**)&wpl,   g_Wp_lo);
    cudaGetSymbolAddress((void**)&wct16, g_WcT16);

    cudaFuncSetAttribute(mma_gemm_bf16,
                         cudaFuncAttributeMaxDynamicSharedMemorySize, G_SMEM_BYTES);
    cudaFuncSetAttribute(mma_gemm_f16<false>,
                         cudaFuncAttributeMaxDynamicSharedMemorySize, G2_SMEM_BYTES);
    cudaFuncSetAttribute(mma_gemm_f16<true>,
                         cudaFuncAttributeMaxDynamicSharedMemorySize, G2_SMEM_BYTES);

    cudaMemcpyAsync(cbuf, c, (size_t)BH * sizeof(float),
                    cudaMemcpyDeviceToDevice, 0);

    // pre-pass
    split_kernel<<<512, 256>>>(W_proj, wph, wpl, (long)H_SZ * H_SZ);
    split16_kernel<<<2048, 256>>>(emb, e16h, e16l, (long)O_SZ * H_SZ);
    split_kernel<<<64, 256>>>(h, resh, resl, (long)BH);   // slot 0 = h_{-1}
    transpose_split_kernel<<<dim3(H4 / 32, H_SZ / 32), 256>>>(W_x, wxth, wxtl, H_SZ, H4);
    transpose_split_kernel<<<dim3(H4 / 32, H_SZ / 32), 256>>>(W_h, whth, whtl, H_SZ, H4);
    transpose16_kernel<<<dim3((O_SZ + 31) / 32, H_SZ / 32), 256>>>(W_out, wot16, H_SZ, O_SZ);
    bc_kernel<<<(H4 + 255) / 256, 256>>>(b_proj, W_x, b_lstm, bc);

    // WcT[j,k] = sum_m W_x[m,j] * W_proj[k,m]  (bf16x3, out fp16)
    mma_gemm_bf16<<<dim3(H_SZ / 128, H4 / 128), 256, G_SMEM_BYTES>>>(
        wxth, wxtl, wph, wpl, wct16, H4, H_SZ);

    // px = emb[x] @ WcT^T + bc   [TB, 4H] fp32  (fp16x2)
    mma_gemm_f16<true><<<dim3(H4 / 256, TB / 128), 256, G2_SMEM_BYTES>>>(
        e16h, e16l, wct16, x, bc, px, TB, H4);

    // sequential LSTM scan
    float* hf_out = out + (size_t)TB * O_SZ;
    float* cf_out = hf_out + BH;
    for (int t = 0; t < T_STEPS; t++) {
        lstm_step_mma<<<128, 128>>>(
            whth, whtl,
            resh + (size_t)t * BH, resl + (size_t)t * BH,
            px + (size_t)t * B_SZ * H4,
            resh + (size_t)(t + 1) * BH, resl + (size_t)(t + 1) * BH,
            r16h + (size_t)t * BH, r16l + (size_t)t * BH,
            hf_out, cf_out, (t == T_STEPS - 1) ? 1 : 0);
    }

    // out = res @ W_out^T + b_out   [TB, O] fp32  (fp16x2)
    mma_gemm_f16<false><<<dim3((O_SZ + 255) / 256, TB / 128), 256, G2_SMEM_BYTES>>>(
        r16h, r16l, wot16, nullptr, b_out, out, TB, O_SZ);
}

// round 6
// speedup vs baseline: 2.7300x; 1.0410x over previous
#include <cuda_runtime.h>
#include <cuda_bf16.h>
#include <cuda_fp16.h>
#include <cstdint>
#include <math.h>

#define T_STEPS 256
#define B_SZ 64
#define H_SZ 1024
#define H4 4096
#define O_SZ 10000
#define TB (T_STEPS * B_SZ)
#define BH (B_SZ * H_SZ)
#define N_CHUNK 16
#define T_PER_CHUNK (T_STEPS / N_CHUNK)

// ===================== low-level helpers (sm_80+ features only) =============
__device__ __forceinline__ uint32_t smem_u32(const void* p) {
    uint32_t a;
    asm("{ .reg .u64 t; cvta.to.shared.u64 t, %1; cvt.u32.u64 %0, t; }"
        : "=r"(a) : "l"(p));
    return a;
}
__device__ __forceinline__ void ldsm4(uint32_t* r, uint32_t a) {
    asm volatile("ldmatrix.sync.aligned.m8n8.x4.shared.b16 {%0,%1,%2,%3}, [%4];"
                 : "=r"(r[0]), "=r"(r[1]), "=r"(r[2]), "=r"(r[3]) : "r"(a));
}
__device__ __forceinline__ void mma_bf16(float* c, const uint32_t* a,
                                         uint32_t b0, uint32_t b1) {
    asm volatile(
        "mma.sync.aligned.m16n8k16.row.col.f32.bf16.bf16.f32 "
        "{%0,%1,%2,%3}, {%4,%5,%6,%7}, {%8,%9}, {%0,%1,%2,%3};"
        : "+f"(c[0]), "+f"(c[1]), "+f"(c[2]), "+f"(c[3])
        : "r"(a[0]), "r"(a[1]), "r"(a[2]), "r"(a[3]), "r"(b0), "r"(b1));
}
__device__ __forceinline__ void mma_f16(float* c, const uint32_t* a,
                                        uint32_t b0, uint32_t b1) {
    asm volatile(
        "mma.sync.aligned.m16n8k16.row.col.f32.f16.f16.f32 "
        "{%0,%1,%2,%3}, {%4,%5,%6,%7}, {%8,%9}, {%0,%1,%2,%3};"
        : "+f"(c[0]), "+f"(c[1]), "+f"(c[2]), "+f"(c[3])
        : "r"(a[0]), "r"(a[1]), "r"(a[2]), "r"(a[3]), "r"(b0), "r"(b1));
}
__device__ __forceinline__ void cp16(uint32_t dst, const void* src, uint32_t sz) {
    asm volatile("cp.async.cg.shared.global [%0], [%1], 16, %2;"
                 :: "r"(dst), "l"(src), "r"(sz) : "memory");
}
#define CP_COMMIT() asm volatile("cp.async.commit_group;" ::: "memory")
#define CP_WAIT1()  asm volatile("cp.async.wait_group 1;" ::: "memory")

__device__ __forceinline__ void split_bf(float x, __nv_bfloat16& hi, __nv_bfloat16& lo) {
    hi = __float2bfloat16(x);
    lo = __float2bfloat16(x - __bfloat162float(hi));
}
__device__ __forceinline__ void split_h16(float x, __half& hi, __half& lo) {
    hi = __float2half(x);
    lo = __float2half(x - __half2float(hi));
}

// ===================== scratch (device globals) ==============================
__device__ float          g_px[(size_t)TB * H4];
__device__ float          g_c[BH];
__device__ float          g_bc[H4];
__device__ __half         g_res16h[(size_t)(T_STEPS + 1) * BH];
__device__ __half         g_res16l[(size_t)(T_STEPS + 1) * BH];
__device__ __half         g_emb16h[(size_t)O_SZ * H_SZ], g_emb16l[(size_t)O_SZ * H_SZ];
__device__ __nv_bfloat16  g_WxT_hi[(size_t)H4 * H_SZ],   g_WxT_lo[(size_t)H4 * H_SZ];
__device__ __half         g_WhT16[(size_t)H4 * H_SZ];
__device__ __half         g_WoT16[(size_t)O_SZ * H_SZ];
__device__ __nv_bfloat16  g_Wp_hi[(size_t)H_SZ * H_SZ],  g_Wp_lo[(size_t)H_SZ * H_SZ];
__device__ __half         g_WcT16[(size_t)H4 * H_SZ];

// ===================== static streams/events (no device mem) ================
static cudaStream_t g_s1;
static cudaEvent_t  g_evPre, g_evDone, g_evPx[N_CHUNK], g_evScan[N_CHUNK];
namespace {
struct StreamInit {
    StreamInit() {
        cudaStreamCreateWithFlags(&g_s1, cudaStreamNonBlocking);
        cudaEventCreateWithFlags(&g_evPre,  cudaEventDisableTiming);
        cudaEventCreateWithFlags(&g_evDone, cudaEventDisableTiming);
        for (int i = 0; i < N_CHUNK; i++) {
            cudaEventCreateWithFlags(&g_evPx[i],   cudaEventDisableTiming);
            cudaEventCreateWithFlags(&g_evScan[i], cudaEventDisableTiming);
        }
    }
};
StreamInit g_streamInit;
}

// ===================== pre-pass kernels ======================================
__global__ void split_kernel(const float* __restrict__ in,
                             __nv_bfloat16* __restrict__ hi,
                             __nv_bfloat16* __restrict__ lo, long n) {
    long i = (long)blockIdx.x * blockDim.x + threadIdx.x;
    long stride = (long)gridDim.x * blockDim.x;
    for (; i < n; i += stride) split_bf(in[i], hi[i], lo[i]);
}
__global__ void split16_kernel(const float* __restrict__ in,
                               __half* __restrict__ hi,
                               __half* __restrict__ lo, long n) {
    long i = (long)blockIdx.x * blockDim.x + threadIdx.x;
    long stride = (long)gridDim.x * blockDim.x;
    for (; i < n; i += stride) split_h16(in[i], hi[i], lo[i]);
}
// [R x C] fp32 -> [C x R] bf16 hi/lo
__global__ void transpose_split_kernel(const float* __restrict__ in,
                                       __nv_bfloat16* __restrict__ hiT,
                                       __nv_bfloat16* __restrict__ loT,
                                       int R, int C) {
    __shared__ float ts[32][33];
    int c0 = blockIdx.x * 32, r0 = blockIdx.y * 32;
    int tx = threadIdx.x & 31, ty = threadIdx.x >> 5;
    for (int rr = ty; rr < 32; rr += 8) {
        int r = r0 + rr, c = c0 + tx;
        ts[rr][tx] = (r < R && c < C) ? in[(size_t)r * C + c] : 0.f;
    }
    __syncthreads();
    for (int cc = ty; cc < 32; cc += 8) {
        int c = c0 + cc, r = r0 + tx;
        if (c < C && r < R) {
            __nv_bfloat16 h, l;
            split_bf(ts[tx][cc], h, l);
            hiT[(size_t)c * R + r] = h;
            loT[(size_t)c * R + r] = l;
        }
    }
}
// [R x C] fp32 -> [C x R] fp16 (single)
__global__ void transpose16_kernel(const float* __restrict__ in,
                                   __half* __restrict__ hiT, int R, int C) {
    __shared__ float ts[32][33];
    int c0 = blockIdx.x * 32, r0 = blockIdx.y * 32;
    int tx = threadIdx.x & 31, ty = threadIdx.x >> 5;
    for (int rr = ty; rr < 32; rr += 8) {
        int r = r0 + rr, c = c0 + tx;
        ts[rr][tx] = (r < R && c < C) ? in[(size_t)r * C + c] : 0.f;
    }
    __syncthreads();
    for (int cc = ty; cc < 32; cc += 8) {
        int c = c0 + cc, r = r0 + tx;
        if (c < C && r < R) hiT[(size_t)c * R + r] = __float2half(ts[tx][cc]);
    }
}
__global__ void bc_kernel(const float* __restrict__ b_proj,
                          const float* __restrict__ W_x,
                          const float* __restrict__ b_lstm,
                          float* __restrict__ bc) {
    int n = blockIdx.x * blockDim.x + threadIdx.x;
    if (n >= H4) return;
    float s = b_lstm[n];
    for (int k = 0; k < H_SZ; k++) s += b_proj[k] * W_x[(size_t)k * H4 + n];
    bc[n] = s;
}

// ===================== bf16x3 GEMM (128x128) — Wc only ======================
#define G_SMEM_BYTES (2 * 40960)
__global__ __launch_bounds__(256, 1)
void mma_gemm_bf16(const __nv_bfloat16* __restrict__ Ah, const __nv_bfloat16* __restrict__ Al,
                   const __nv_bfloat16* __restrict__ Bh, const __nv_bfloat16* __restrict__ Bl,
                   __half* __restrict__ C16, int M, int N)
{
    extern __shared__ __align__(16) char smem[];
    const uint32_t sb = smem_u32(smem);
    const int tid = threadIdx.x, lane = tid & 31, wid = tid >> 5;
    const int bm = blockIdx.y * 128, bn = blockIdx.x * 128;
    const int wm = (wid >> 2) * 64, wn = (wid & 3) * 32;

    long a_off[2], b_off[2];
    uint32_t a_s[2], b_s[2], b_sz[2];
#pragma unroll
    for (int q = 0; q < 2; q++) {
        int pos = q * 256 + tid;
        int r = pos >> 2, c8 = (pos & 3) * 8;
        a_off[q] = (long)(bm + r) * H_SZ + c8;
        a_s[q] = (uint32_t)(r * 80 + (pos & 3) * 16);
        int gn = bn + r;
        b_sz[q]  = (gn < N) ? 16u : 0u;
        b_off[q] = (long)((gn < N) ? gn : 0) * H_SZ + c8;
        b_s[q] = a_s[q];
    }

    float acc[4][4][4];
#pragma unroll
    for (int m = 0; m < 4; m++)
#pragma unroll
        for (int j = 0; j < 4; j++)
#pragma unroll
            for (int q = 0; q < 4; q++) acc[m][j][q] = 0.f;

#define GB_LOAD(ck, s) do {                                                   \
    const long ko = (long)(ck) * 32;                                          \
    const uint32_t st = sb + (s) * 40960;                                     \
    _Pragma("unroll")                                                         \
    for (int q = 0; q < 2; q++) {                                             \
        cp16(st + a_s[q],         Ah + a_off[q] + ko, 16u);                   \
        cp16(st + 10240 + a_s[q], Al + a_off[q] + ko, 16u);                   \
        cp16(st + 20480 + b_s[q], Bh + b_off[q] + ko, b_sz[q]);               \
        cp16(st + 30720 + b_s[q], Bl + b_off[q] + ko, b_sz[q]);               \
    }                                                                         \
} while (0)

    GB_LOAD(0, 0); CP_COMMIT();
    GB_LOAD(1, 1); CP_COMMIT();

    for (int ck = 0; ck < 32; ck++) {
        const int s = ck & 1;
        CP_WAIT1();
        __syncthreads();
        const uint32_t sA = sb + s * 40960;
        const uint32_t sB = sA + 20480;
#pragma unroll
        for (int ks = 0; ks < 2; ks++) {
            uint32_t ah[4][4], al[4][4], bh[8], bl[8];
            const int arow = lane & 15;
            const uint32_t ac = (uint32_t)(((lane >> 4) * 8 + ks * 16) * 2);
#pragma unroll
            for (int mf = 0; mf < 4; mf++) {
                uint32_t ad = sA + (uint32_t)((wm + mf * 16 + arow) * 80) + ac;
                ldsm4(ah[mf], ad);
                ldsm4(al[mf], ad + 10240);
            }
            const int brow = (lane & 7) + ((lane >> 4) & 1) * 8;
            const uint32_t bcd = (uint32_t)(((((lane >> 3) & 1) * 8) + ks * 16) * 2);
#pragma unroll
            for (int pf = 0; pf < 2; pf++) {
                uint32_t bd = sB + (uint32_t)((wn + pf * 16 + brow) * 80) + bcd;
                ldsm4(&bh[pf * 4], bd);
                ldsm4(&bl[pf * 4], bd + 10240);
            }
#pragma unroll
            for (int m = 0; m < 4; m++)
#pragma unroll
                for (int j = 0; j < 4; j++) {
                    const int bi = (j >> 1) * 4 + (j & 1) * 2;
                    mma_bf16(acc[m][j], ah[m], bh[bi], bh[bi + 1]);
                    mma_bf16(acc[m][j], al[m], bh[bi], bh[bi + 1]);
                    mma_bf16(acc[m][j], ah[m], bl[bi], bl[bi + 1]);
                }
        }
        __syncthreads();
        if (ck + 2 < 32) GB_LOAD(ck + 2, s);
        CP_COMMIT();
    }

#pragma unroll
    for (int m = 0; m < 4; m++) {
        const int r0 = bm + wm + m * 16 + (lane >> 2);
#pragma unroll
        for (int j = 0; j < 4; j++) {
            const int col = bn + wn + j * 8 + (lane & 3) * 2;
#pragma unroll
            for (int hh = 0; hh < 2; hh++) {
                const int r = r0 + hh * 8;
                if (col < N)     C16[(size_t)r * N + col]     = __float2half(acc[m][j][hh * 2 + 0]);
                if (col + 1 < N) C16[(size_t)r * N + col + 1] = __float2half(acc[m][j][hh * 2 + 1]);
            }
        }
    }
#undef GB_LOAD
}

// ===================== fp16x2 GEMM (128x256) — px and out chunks ============
#define G2_SMEM_BYTES (2 * 40960)
template <bool GATHER>
__global__ __launch_bounds__(256, 1)
void mma_gemm_f16(const __half* __restrict__ Ah, const __half* __restrict__ Al,
                  const __half* __restrict__ Bh,
                  const int* __restrict__ gidx, const float* __restrict__ bias,
                  float* __restrict__ C, int M, int N)
{
    extern __shared__ __align__(16) char smem[];
    const uint32_t sb = smem_u32(smem);
    const int tid = threadIdx.x, lane = tid & 31, wid = tid >> 5;
    const int bm = blockIdx.y * 128, bn = blockIdx.x * 256;
    const int wm = (wid >> 2) * 64, wn = (wid & 3) * 64;

    long a_off[2];
    uint32_t a_s[2];
#pragma unroll
    for (int q = 0; q < 2; q++) {
        int pos = q * 256 + tid;
        int r = pos >> 2, c8 = (pos & 3) * 8;
        long ar = GATHER ? (long)gidx[bm + r] : (long)(bm + r);
        a_off[q] = ar * H_SZ + c8;
        a_s[q] = (uint32_t)(r * 80 + (pos & 3) * 16);
    }
    long b_off[4];
    uint32_t b_s[4], b_sz[4];
#pragma unroll
    for (int q = 0; q < 4; q++) {
        int pos = q * 256 + tid;
        int r = pos >> 2, c8 = (pos & 3) * 8;
        int gn = bn + r;
        b_sz[q]  = (gn < N) ? 16u : 0u;
        b_off[q] = (long)((gn < N) ? gn : 0) * H_SZ + c8;
        b_s[q] = (uint32_t)(r * 80 + (pos & 3) * 16);
    }

    float acc[4][8][4];
#pragma unroll
    for (int m = 0; m < 4; m++)
#pragma unroll
        for (int j = 0; j < 8; j++)
#pragma unroll
            for (int q = 0; q < 4; q++) acc[m][j][q] = 0.f;

#define G2_LOAD(ck, s) do {                                                   \
    const long ko = (long)(ck) * 32;                                          \
    const uint32_t st = sb + (s) * 40960;                                     \
    _Pragma("unroll")                                                         \
    for (int q = 0; q < 2; q++) {                                             \
        cp16(st + a_s[q],         Ah + a_off[q] + ko, 16u);                   \
        cp16(st + 10240 + a_s[q], Al + a_off[q] + ko, 16u);                   \
    }                                                                         \
    _Pragma("unroll")                                                         \
    for (int q = 0; q < 4; q++)                                               \
        cp16(st + 20480 + b_s[q], Bh + b_off[q] + ko, b_sz[q]);               \
} while (0)

    G2_LOAD(0, 0); CP_COMMIT();
    G2_LOAD(1, 1); CP_COMMIT();

    for (int ck = 0; ck < 32; ck++) {
        const int s = ck & 1;
        CP_WAIT1();
        __syncthreads();
        const uint32_t sA = sb + s * 40960;
        const uint32_t sB = sA + 20480;
#pragma unroll
        for (int ks = 0; ks < 2; ks++) {
            uint32_t ah[4][4], al[4][4], bh[16];
            const int arow = lane & 15;
            const uint32_t ac = (uint32_t)(((lane >> 4) * 8 + ks * 16) * 2);
#pragma unroll
            for (int mf = 0; mf < 4; mf++) {
                uint32_t ad = sA + (uint32_t)((wm + mf * 16 + arow) * 80) + ac;
                ldsm4(ah[mf], ad);
                ldsm4(al[mf], ad + 10240);
            }
            const int brow = (lane & 7) + ((lane >> 4) & 1) * 8;
            const uint32_t bcd = (uint32_t)(((((lane >> 3) & 1) * 8) + ks * 16) * 2);
#pragma unroll
            for (int pf = 0; pf < 4; pf++) {
                uint32_t bd = sB + (uint32_t)((wn + pf * 16 + brow) * 80) + bcd;
                ldsm4(&bh[pf * 4], bd);
            }
#pragma unroll
            for (int m = 0; m < 4; m++)
#pragma unroll
                for (int j = 0; j < 8; j++) {
                    const int bi = (j >> 1) * 4 + (j & 1) * 2;
                    mma_f16(acc[m][j], ah[m], bh[bi], bh[bi + 1]);
                    mma_f16(acc[m][j], al[m], bh[bi], bh[bi + 1]);
                }
        }
        __syncthreads();
        if (ck + 2 < 32) G2_LOAD(ck + 2, s);
        CP_COMMIT();
    }

#pragma unroll
    for (int m = 0; m < 4; m++) {
        const int r0 = bm + wm + m * 16 + (lane >> 2);
#pragma unroll
        for (int j = 0; j < 8; j++) {
            const int col = bn + wn + j * 8 + (lane & 3) * 2;
#pragma unroll
            for (int hh = 0; hh < 2; hh++) {
                const int r = r0 + hh * 8;
                if (col < N)     C[(size_t)r * N + col]     = acc[m][j][hh * 2 + 0] + bias[col];
                if (col + 1 < N) C[(size_t)r * N + col + 1] = acc[m][j][hh * 2 + 1] + bias[col + 1];
            }
        }
    }
#undef G2_LOAD
}

// ===================== fused LSTM step (fp16x2 mma.sync) =====================
// CTA = 8 units x 4 gates (M=32) x 64 batch, K=1024. 4 warps 2x2, warp 16x32.
// W_h fp16 single; h fp16 hi/lo (2 MMA passes).
// SMEM stage: A 0 (2560B), Bh 2560 (5120B), Bl 7680 (5120B); stage 12800, x2.
__global__ __launch_bounds__(128, 1)
void lstm_step_mma(const __half* __restrict__ WhT16,
                   const __half* __restrict__ hh,
                   const __half* __restrict__ hl,
                   const float* __restrict__ px_t,
                   __half* __restrict__ oh, __half* __restrict__ ol,
                   float* __restrict__ hf, float* __restrict__ cf, int last)
{
    __shared__ __align__(16) char smem[25600];
    const uint32_t sb = smem_u32(smem);
    const int tid = threadIdx.x, lane = tid & 31, wid = tid >> 5;
    const int u0 = blockIdx.x * 8;
    const int wm = (wid >> 1) * 16, wn = (wid & 1) * 32;

    long a_off;
    uint32_t a_s;
    {
        int r = tid >> 2, c8 = (tid & 3) * 8;     // r: 0..31
        long grow = (long)(r >> 3) * H_SZ + u0 + (r & 7);
        a_off = grow * H_SZ + c8;
        a_s = (uint32_t)(r * 80 + (tid & 3) * 16);
    }
    long b_off[2];
    uint32_t b_s[2];
#pragma unroll
    for (int q = 0; q < 2; q++) {
        int pos = q * 128 + tid;
        int r = pos >> 2, c8 = (pos & 3) * 8;     // r: 0..63
        b_off[q] = (long)r * H_SZ + c8;
        b_s[q] = (uint32_t)(r * 80 + (pos & 3) * 16);
    }

    float acc[4][4];
#pragma unroll
    for (int j = 0; j < 4; j++)
#pragma unroll
        for (int q = 0; q < 4; q++) acc[j][q] = 0.f;

#define S_LOAD(ck, s) do {                                                    \
    const long ko = (long)(ck) * 32;                                          \
    const uint32_t st = sb + (s) * 12800;                                     \
    cp16(st + a_s, WhT16 + a_off + ko, 16u);                                  \
    _Pragma("unroll")                                                         \
    for (int q = 0; q < 2; q++) {                                             \
        cp16(st + 2560 + b_s[q], hh + b_off[q] + ko, 16u);                    \
        cp16(st + 7680 + b_s[q], hl + b_off[q] + ko, 16u);                    \
    }                                                                         \
} while (0)

    S_LOAD(0, 0); CP_COMMIT();
    S_LOAD(1, 1); CP_COMMIT();

    for (int ck = 0; ck < 32; ck++) {
        const int s = ck & 1;
        CP_WAIT1();
        __syncthreads();
        const uint32_t sA = sb + s * 12800;
        const uint32_t sB = sA + 2560;
#pragma unroll
        for (int ks = 0; ks < 2; ks++) {
            uint32_t ah[4], bh[8], bl[8];
            const uint32_t ac = (uint32_t)(((lane >> 4) * 8 + ks * 16) * 2);
            {
                uint32_t ad = sA + (uint32_t)((wm + (lane & 15)) * 80) + ac;
                ldsm4(ah, ad);
            }
            const int brow = (lane & 7) + ((lane >> 4) & 1) * 8;
            const uint32_t bcd = (uint32_t)(((((lane >> 3) & 1) * 8) + ks * 16) * 2);
#pragma unroll
            for (int pf = 0; pf < 2; pf++) {
                uint32_t bd = sB + (uint32_t)((wn + pf * 16 + brow) * 80) + bcd;
                ldsm4(&bh[pf * 4], bd);
                ldsm4(&bl[pf * 4], bd + 5120);
            }
#pragma unroll
            for (int j = 0; j < 4; j++) {
                const int bi = (j >> 1) * 4 + (j & 1) * 2;
                mma_f16(acc[j], ah, bh[bi], bh[bi + 1]);
                mma_f16(acc[j], ah, bl[bi], bl[bi + 1]);
            }
        }
        __syncthreads();
        if (ck + 2 < 32) S_LOAD(ck + 2, s);
        CP_COMMIT();
    }

    __syncthreads();
    float* Gs = (float*)smem;   // [32][65]
    {
        const int row = wm + (lane >> 2);
#pragma unroll
        for (int j = 0; j < 4; j++) {
            const int col = wn + j * 8 + (lane & 3) * 2;
            Gs[row * 65 + col]           = acc[j][0];
            Gs[row * 65 + col + 1]       = acc[j][1];
            Gs[(row + 8) * 65 + col]     = acc[j][2];
            Gs[(row + 8) * 65 + col + 1] = acc[j][3];
        }
    }
    __syncthreads();

    {
        const int u = tid & 7;
        const int b0 = (tid >> 3) * 4;
        const int gu = u0 + u;
#pragma unroll
        for (int jj = 0; jj < 4; jj++) {
            const int b = b0 + jj;
            const float* pxb = px_t + (size_t)b * H4;
            float gi = Gs[(0 * 8 + u) * 65 + b] + pxb[gu];
            float gf = Gs[(1 * 8 + u) * 65 + b] + pxb[1024 + gu];
            float gg = Gs[(2 * 8 + u) * 65 + b] + pxb[2048 + gu];
            float go = Gs[(3 * 8 + u) * 65 + b] + pxb[3072 + gu];
            float si = 1.f / (1.f + expf(-gi));
            float sf = 1.f / (1.f + expf(-gf));
            float so = 1.f / (1.f + expf(-go));
            float tg = tanhf(gg);
            const int ci = b * H_SZ + gu;
            float cn = sf * g_c[ci] + si * tg;
            float hn = so * tanhf(cn);
            g_c[ci] = cn;
            __half vh, vl;
            split_h16(hn, vh, vl);
            oh[ci] = vh; ol[ci] = vl;
            if (last) { hf[ci] = hn; cf[ci] = cn; }
        }
    }
#undef S_LOAD
}

// ===================== launch ================================================
extern "C" void kernel_launch(void* const* d_in, const int* in_sizes, int n_in,
                              void* d_out, int out_size)
{
    const int*   x      = (const int*)  d_in[0];
    const float* h      = (const float*)d_in[1];
    const float* c      = (const float*)d_in[2];
    const float* emb    = (const float*)d_in[3];
    const float* W_proj = (const float*)d_in[4];
    const float* b_proj = (const float*)d_in[5];
    const float* W_x    = (const float*)d_in[6];
    const float* W_h    = (const float*)d_in[7];
    const float* b_lstm = (const float*)d_in[8];
    const float* W_out  = (const float*)d_in[9];
    const float* b_out  = (const float*)d_in[10];
    float* out = (float*)d_out;

    float *px, *cbuf, *bc;
    __nv_bfloat16 *wxth, *wxtl, *wph, *wpl;
    __half *r16h, *r16l, *e16h, *e16l, *wht16, *wot16, *wct16;
    cudaGetSymbolAddress((void**)&px,    g_px);
    cudaGetSymbolAddress((void**)&cbuf,  g_c);
    cudaGetSymbolAddress((void**)&bc,    g_bc);
    cudaGetSymbolAddress((void**)&r16h,  g_res16h);
    cudaGetSymbolAddress((void**)&r16l,  g_res16l);
    cudaGetSymbolAddress((void**)&e16h,  g_emb16h);
    cudaGetSymbolAddress((void**)&e16l,  g_emb16l);
    cudaGetSymbolAddress((void**)&wxth,  g_WxT_hi);
    cudaGetSymbolAddress((void**)&wxtl,  g_WxT_lo);
    cudaGetSymbolAddress((void**)&wht16, g_WhT16);
    cudaGetSymbolAddress((void**)&wot16, g_WoT16);
    cudaGetSymbolAddress((void**)&wph,   g_Wp_hi);
    cudaGetSymbolAddress((void**)&wpl,   g_Wp_lo);
    cudaGetSymbolAddress((void**)&wct16, g_WcT16);

    cudaFuncSetAttribute(mma_gemm_bf16,
                         cudaFuncAttributeMaxDynamicSharedMemorySize, G_SMEM_BYTES);
    cudaFuncSetAttribute(mma_gemm_f16<false>,
                         cudaFuncAttributeMaxDynamicSharedMemorySize, G2_SMEM_BYTES);
    cudaFuncSetAttribute(mma_gemm_f16<true>,
                         cudaFuncAttributeMaxDynamicSharedMemorySize, G2_SMEM_BYTES);

    // ---------- prepass on stream 0 ----------
    cudaMemcpyAsync(cbuf, c, (size_t)BH * sizeof(float),
                    cudaMemcpyDeviceToDevice, 0);
    split_kernel<<<512, 256>>>(W_proj, wph, wpl, (long)H_SZ * H_SZ);
    split16_kernel<<<2048, 256>>>(emb, e16h, e16l, (long)O_SZ * H_SZ);
    split16_kernel<<<64, 256>>>(h, r16h, r16l, (long)BH);   // slab 0 = h_{-1}
    transpose_split_kernel<<<dim3(H4 / 32, H_SZ / 32), 256>>>(W_x, wxth, wxtl, H_SZ, H4);
    transpose16_kernel<<<dim3(H4 / 32, H_SZ / 32), 256>>>(W_h, wht16, H_SZ, H4);
    transpose16_kernel<<<dim3((O_SZ + 31) / 32, H_SZ / 32), 256>>>(W_out, wot16, H_SZ, O_SZ);
    bc_kernel<<<(H4 + 255) / 256, 256>>>(b_proj, W_x, b_lstm, bc);

    cudaEventRecord(g_evPre, 0);
    cudaStreamWaitEvent(g_s1, g_evPre, 0);

    // ---------- Wc + px chunks on s1 ----------
    mma_gemm_bf16<<<dim3(H_SZ / 128, H4 / 128), 256, G_SMEM_BYTES, g_s1>>>(
        wxth, wxtl, wph, wpl, wct16, H4, H_SZ);

    for (int k = 0; k < N_CHUNK; k++) {
        const int rows = T_PER_CHUNK * B_SZ;   // 1024
        mma_gemm_f16<true><<<dim3(H4 / 256, rows / 128), 256, G2_SMEM_BYTES, g_s1>>>(
            e16h, e16l, wct16, x + (size_t)k * rows, bc,
            px + (size_t)k * rows * H4, rows, H4);
        cudaEventRecord(g_evPx[k], g_s1);
    }

    // ---------- sequential LSTM scan on stream 0 ----------
    float* hf_out = out + (size_t)TB * O_SZ;
    float* cf_out = hf_out + BH;
    for (int t = 0; t < T_STEPS; t++) {
        if ((t % T_PER_CHUNK) == 0)
            cudaStreamWaitEvent(0, g_evPx[t / T_PER_CHUNK], 0);
        lstm_step_mma<<<128, 128>>>(
            wht16,
            r16h + (size_t)t * BH, r16l + (size_t)t * BH,
            px + (size_t)t * B_SZ * H4,
            r16h + (size_t)(t + 1) * BH, r16l + (size_t)(t + 1) * BH,
            hf_out, cf_out, (t == T_STEPS - 1) ? 1 : 0);
        if ((t % T_PER_CHUNK) == T_PER_CHUNK - 1)
            cudaEventRecord(g_evScan[t / T_PER_CHUNK], 0);
    }

    // ---------- out chunks on s1, overlapping the scan ----------
    for (int k = 0; k < N_CHUNK; k++) {
        const int rows = T_PER_CHUNK * B_SZ;   // 1024
        cudaStreamWaitEvent(g_s1, g_evScan[k], 0);
        mma_gemm_f16<false><<<dim3((O_SZ + 255) / 256, rows / 128), 256, G2_SMEM_BYTES, g_s1>>>(
            r16h + BH + (size_t)k * rows * H_SZ,
            r16l + BH + (size_t)k * rows * H_SZ,
            wot16, nullptr, b_out,
            out + (size_t)k * rows * O_SZ, rows, O_SZ);
    }

    cudaEventRecord(g_evDone, g_s1);
    cudaStreamWaitEvent(0, g_evDone, 0);
}

// round 7
// speedup vs baseline: 3.0603x; 1.1210x over previous
#include <cuda_runtime.h>
#include <cuda_bf16.h>
#include <cuda_fp16.h>
#include <cstdint>
#include <math.h>

#define T_STEPS 256
#define B_SZ 64
#define H_SZ 1024
#define H4 4096
#define O_SZ 10000
#define TB (T_STEPS * B_SZ)
#define BH (B_SZ * H_SZ)
#define N_CHUNK 16
#define T_PER_CHUNK (T_STEPS / N_CHUNK)

// ===================== low-level helpers (sm_80+ features only) =============
__device__ __forceinline__ uint32_t smem_u32(const void* p) {
    uint32_t a;
    asm("{ .reg .u64 t; cvta.to.shared.u64 t, %1; cvt.u32.u64 %0, t; }"
        : "=r"(a) : "l"(p));
    return a;
}
__device__ __forceinline__ void ldsm4(uint32_t* r, uint32_t a) {
    asm volatile("ldmatrix.sync.aligned.m8n8.x4.shared.b16 {%0,%1,%2,%3}, [%4];"
                 : "=r"(r[0]), "=r"(r[1]), "=r"(r[2]), "=r"(r[3]) : "r"(a));
}
__device__ __forceinline__ void mma_bf16(float* c, const uint32_t* a,
                                         uint32_t b0, uint32_t b1) {
    asm volatile(
        "mma.sync.aligned.m16n8k16.row.col.f32.bf16.bf16.f32 "
        "{%0,%1,%2,%3}, {%4,%5,%6,%7}, {%8,%9}, {%0,%1,%2,%3};"
        : "+f"(c[0]), "+f"(c[1]), "+f"(c[2]), "+f"(c[3])
        : "r"(a[0]), "r"(a[1]), "r"(a[2]), "r"(a[3]), "r"(b0), "r"(b1));
}
__device__ __forceinline__ void mma_f16(float* c, const uint32_t* a,
                                        uint32_t b0, uint32_t b1) {
    asm volatile(
        "mma.sync.aligned.m16n8k16.row.col.f32.f16.f16.f32 "
        "{%0,%1,%2,%3}, {%4,%5,%6,%7}, {%8,%9}, {%0,%1,%2,%3};"
        : "+f"(c[0]), "+f"(c[1]), "+f"(c[2]), "+f"(c[3])
        : "r"(a[0]), "r"(a[1]), "r"(a[2]), "r"(a[3]), "r"(b0), "r"(b1));
}
__device__ __forceinline__ void cp16(uint32_t dst, const void* src, uint32_t sz) {
    asm volatile("cp.async.cg.shared.global [%0], [%1], 16, %2;"
                 :: "r"(dst), "l"(src), "r"(sz) : "memory");
}
#define CP_COMMIT() asm volatile("cp.async.commit_group;" ::: "memory")
#define CP_WAIT1()  asm volatile("cp.async.wait_group 1;" ::: "memory")

__device__ __forceinline__ void split_bf(float x, __nv_bfloat16& hi, __nv_bfloat16& lo) {
    hi = __float2bfloat16(x);
    lo = __float2bfloat16(x - __bfloat162float(hi));
}
__device__ __forceinline__ void split_h16(float x, __half& hi, __half& lo) {
    hi = __float2half(x);
    lo = __float2half(x - __half2float(hi));
}

// ===================== scratch (device globals) ==============================
__device__ float          g_px[(size_t)TB * H4];
__device__ float          g_c[BH];
__device__ float          g_bc[H4];
__device__ __half         g_res16h[(size_t)(T_STEPS + 1) * BH];
__device__ __half         g_res16l[(size_t)(T_STEPS + 1) * BH];
__device__ __half         g_emb16h[(size_t)O_SZ * H_SZ];
__device__ __nv_bfloat16  g_WxT_hi[(size_t)H4 * H_SZ],   g_WxT_lo[(size_t)H4 * H_SZ];
__device__ __half         g_WhT16[(size_t)H4 * H_SZ];
__device__ __half         g_WoT16[(size_t)O_SZ * H_SZ];
__device__ __nv_bfloat16  g_Wp_hi[(size_t)H_SZ * H_SZ],  g_Wp_lo[(size_t)H_SZ * H_SZ];
__device__ __half         g_WcT16[(size_t)H4 * H_SZ];

// ===================== static streams/events (no device mem) ================
static cudaStream_t g_s1, g_s2;    // s1 = GEMMs (low prio), s2 = scan (high prio)
static cudaEvent_t  g_evPre, g_evDone1, g_evDone2;
static cudaEvent_t  g_evPx[N_CHUNK], g_evScan[N_CHUNK];
namespace {
struct StreamInit {
    StreamInit() {
        int lo, hi;
        cudaDeviceGetStreamPriorityRange(&lo, &hi);
        cudaStreamCreateWithPriority(&g_s1, cudaStreamNonBlocking, lo);
        cudaStreamCreateWithPriority(&g_s2, cudaStreamNonBlocking, hi);
        cudaEventCreateWithFlags(&g_evPre,   cudaEventDisableTiming);
        cudaEventCreateWithFlags(&g_evDone1, cudaEventDisableTiming);
        cudaEventCreateWithFlags(&g_evDone2, cudaEventDisableTiming);
        for (int i = 0; i < N_CHUNK; i++) {
            cudaEventCreateWithFlags(&g_evPx[i],   cudaEventDisableTiming);
            cudaEventCreateWithFlags(&g_evScan[i], cudaEventDisableTiming);
        }
    }
};
StreamInit g_streamInit;
}

// ===================== pre-pass kernels ======================================
__global__ void split_kernel(const float* __restrict__ in,
                             __nv_bfloat16* __restrict__ hi,
                             __nv_bfloat16* __restrict__ lo, long n) {
    long i = (long)blockIdx.x * blockDim.x + threadIdx.x;
    long stride = (long)gridDim.x * blockDim.x;
    for (; i < n; i += stride) split_bf(in[i], hi[i], lo[i]);
}
__global__ void split16_kernel(const float* __restrict__ in,
                               __half* __restrict__ hi,
                               __half* __restrict__ lo, long n) {
    long i = (long)blockIdx.x * blockDim.x + threadIdx.x;
    long stride = (long)gridDim.x * blockDim.x;
    for (; i < n; i += stride) split_h16(in[i], hi[i], lo[i]);
}
__global__ void conv16_kernel(const float* __restrict__ in,
                              __half* __restrict__ o, long n) {
    long i = (long)blockIdx.x * blockDim.x + threadIdx.x;
    long stride = (long)gridDim.x * blockDim.x;
    for (; i < n; i += stride) o[i] = __float2half(in[i]);
}
// [R x C] fp32 -> [C x R] bf16 hi/lo
__global__ void transpose_split_kernel(const float* __restrict__ in,
                                       __nv_bfloat16* __restrict__ hiT,
                                       __nv_bfloat16* __restrict__ loT,
                                       int R, int C) {
    __shared__ float ts[32][33];
    int c0 = blockIdx.x * 32, r0 = blockIdx.y * 32;
    int tx = threadIdx.x & 31, ty = threadIdx.x >> 5;
    for (int rr = ty; rr < 32; rr += 8) {
        int r = r0 + rr, c = c0 + tx;
        ts[rr][tx] = (r < R && c < C) ? in[(size_t)r * C + c] : 0.f;
    }
    __syncthreads();
    for (int cc = ty; cc < 32; cc += 8) {
        int c = c0 + cc, r = r0 + tx;
        if (c < C && r < R) {
            __nv_bfloat16 h, l;
            split_bf(ts[tx][cc], h, l);
            hiT[(size_t)c * R + r] = h;
            loT[(size_t)c * R + r] = l;
        }
    }
}
// [R x C] fp32 -> [C x R] fp16
__global__ void transpose16_kernel(const float* __restrict__ in,
                                   __half* __restrict__ hiT, int R, int C) {
    __shared__ float ts[32][33];
    int c0 = blockIdx.x * 32, r0 = blockIdx.y * 32;
    int tx = threadIdx.x & 31, ty = threadIdx.x >> 5;
    for (int rr = ty; rr < 32; rr += 8) {
        int r = r0 + rr, c = c0 + tx;
        ts[rr][tx] = (r < R && c < C) ? in[(size_t)r * C + c] : 0.f;
    }
    __syncthreads();
    for (int cc = ty; cc < 32; cc += 8) {
        int c = c0 + cc, r = r0 + tx;
        if (c < C && r < R) hiT[(size_t)c * R + r] = __float2half(ts[tx][cc]);
    }
}
__global__ void bc_kernel(const float* __restrict__ b_proj,
                          const float* __restrict__ W_x,
                          const float* __restrict__ b_lstm,
                          float* __restrict__ bc) {
    int n = blockIdx.x * blockDim.x + threadIdx.x;
    if (n >= H4) return;
    float s = b_lstm[n];
    for (int k = 0; k < H_SZ; k++) s += b_proj[k] * W_x[(size_t)k * H4 + n];
    bc[n] = s;
}

// ===================== bf16x3 GEMM (128x128) — Wc only ======================
#define G_SMEM_BYTES (2 * 40960)
__global__ __launch_bounds__(256, 1)
void mma_gemm_bf16(const __nv_bfloat16* __restrict__ Ah, const __nv_bfloat16* __restrict__ Al,
                   const __nv_bfloat16* __restrict__ Bh, const __nv_bfloat16* __restrict__ Bl,
                   __half* __restrict__ C16, int M, int N)
{
    extern __shared__ __align__(16) char smem[];
    const uint32_t sb = smem_u32(smem);
    const int tid = threadIdx.x, lane = tid & 31, wid = tid >> 5;
    const int bm = blockIdx.y * 128, bn = blockIdx.x * 128;
    const int wm = (wid >> 2) * 64, wn = (wid & 3) * 32;

    long a_off[2], b_off[2];
    uint32_t a_s[2], b_s[2], b_sz[2];
#pragma unroll
    for (int q = 0; q < 2; q++) {
        int pos = q * 256 + tid;
        int r = pos >> 2, c8 = (pos & 3) * 8;
        a_off[q] = (long)(bm + r) * H_SZ + c8;
        a_s[q] = (uint32_t)(r * 80 + (pos & 3) * 16);
        int gn = bn + r;
        b_sz[q]  = (gn < N) ? 16u : 0u;
        b_off[q] = (long)((gn < N) ? gn : 0) * H_SZ + c8;
        b_s[q] = a_s[q];
    }

    float acc[4][4][4];
#pragma unroll
    for (int m = 0; m < 4; m++)
#pragma unroll
        for (int j = 0; j < 4; j++)
#pragma unroll
            for (int q = 0; q < 4; q++) acc[m][j][q] = 0.f;

#define GB_LOAD(ck, s) do {                                                   \
    const long ko = (long)(ck) * 32;                                          \
    const uint32_t st = sb + (s) * 40960;                                     \
    _Pragma("unroll")                                                         \
    for (int q = 0; q < 2; q++) {                                             \
        cp16(st + a_s[q],         Ah + a_off[q] + ko, 16u);                   \
        cp16(st + 10240 + a_s[q], Al + a_off[q] + ko, 16u);                   \
        cp16(st + 20480 + b_s[q], Bh + b_off[q] + ko, b_sz[q]);               \
        cp16(st + 30720 + b_s[q], Bl + b_off[q] + ko, b_sz[q]);               \
    }                                                                         \
} while (0)

    GB_LOAD(0, 0); CP_COMMIT();
    GB_LOAD(1, 1); CP_COMMIT();

    for (int ck = 0; ck < 32; ck++) {
        const int s = ck & 1;
        CP_WAIT1();
        __syncthreads();
        const uint32_t sA = sb + s * 40960;
        const uint32_t sB = sA + 20480;
#pragma unroll
        for (int ks = 0; ks < 2; ks++) {
            uint32_t ah[4][4], al[4][4], bh[8], bl[8];
            const int arow = lane & 15;
            const uint32_t ac = (uint32_t)(((lane >> 4) * 8 + ks * 16) * 2);
#pragma unroll
            for (int mf = 0; mf < 4; mf++) {
                uint32_t ad = sA + (uint32_t)((wm + mf * 16 + arow) * 80) + ac;
                ldsm4(ah[mf], ad);
                ldsm4(al[mf], ad + 10240);
            }
            const int brow = (lane & 7) + ((lane >> 4) & 1) * 8;
            const uint32_t bcd = (uint32_t)(((((lane >> 3) & 1) * 8) + ks * 16) * 2);
#pragma unroll
            for (int pf = 0; pf < 2; pf++) {
                uint32_t bd = sB + (uint32_t)((wn + pf * 16 + brow) * 80) + bcd;
                ldsm4(&bh[pf * 4], bd);
                ldsm4(&bl[pf * 4], bd + 10240);
            }
#pragma unroll
            for (int m = 0; m < 4; m++)
#pragma unroll
                for (int j = 0; j < 4; j++) {
                    const int bi = (j >> 1) * 4 + (j & 1) * 2;
                    mma_bf16(acc[m][j], ah[m], bh[bi], bh[bi + 1]);
                    mma_bf16(acc[m][j], al[m], bh[bi], bh[bi + 1]);
                    mma_bf16(acc[m][j], ah[m], bl[bi], bl[bi + 1]);
                }
        }
        __syncthreads();
        if (ck + 2 < 32) GB_LOAD(ck + 2, s);
        CP_COMMIT();
    }

#pragma unroll
    for (int m = 0; m < 4; m++) {
        const int r0 = bm + wm + m * 16 + (lane >> 2);
#pragma unroll
        for (int j = 0; j < 4; j++) {
            const int col = bn + wn + j * 8 + (lane & 3) * 2;
#pragma unroll
            for (int hh = 0; hh < 2; hh++) {
                const int r = r0 + hh * 8;
                if (col < N)     C16[(size_t)r * N + col]     = __float2half(acc[m][j][hh * 2 + 0]);
                if (col + 1 < N) C16[(size_t)r * N + col + 1] = __float2half(acc[m][j][hh * 2 + 1]);
            }
        }
    }
#undef GB_LOAD
}

// ===================== fp16 GEMM (128x256), 1 or 2 A-passes =================
// C[M,N] = (Ah[+Al])[M,1024] @ Bh[N,1024]^T + bias.  8 warps 2x4, warp 64x64.
// APASS==1 stage: A 0 (10240), B 10240 (20480); stage 30720.
// APASS==2 stage: A 0, Al 10240, B 20480; stage 40960.
template <bool GATHER, int APASS>
__global__ __launch_bounds__(256, 1)
void mma_gemm_f16(const __half* __restrict__ Ah, const __half* __restrict__ Al,
                  const __half* __restrict__ Bh,
                  const int* __restrict__ gidx, const float* __restrict__ bias,
                  float* __restrict__ C, int M, int N)
{
    constexpr uint32_t STG  = (APASS == 2) ? 40960u : 30720u;
    constexpr uint32_t BOFF = (APASS == 2) ? 20480u : 10240u;
    extern __shared__ __align__(16) char smem[];
    const uint32_t sb = smem_u32(smem);
    const int tid = threadIdx.x, lane = tid & 31, wid = tid >> 5;
    const int bm = blockIdx.y * 128, bn = blockIdx.x * 256;
    const int wm = (wid >> 2) * 64, wn = (wid & 3) * 64;

    long a_off[2];
    uint32_t a_s[2];
#pragma unroll
    for (int q = 0; q < 2; q++) {
        int pos = q * 256 + tid;
        int r = pos >> 2, c8 = (pos & 3) * 8;
        long ar = GATHER ? (long)gidx[bm + r] : (long)(bm + r);
        a_off[q] = ar * H_SZ + c8;
        a_s[q] = (uint32_t)(r * 80 + (pos & 3) * 16);
    }
    long b_off[4];
    uint32_t b_s[4], b_sz[4];
#pragma unroll
    for (int q = 0; q < 4; q++) {
        int pos = q * 256 + tid;
        int r = pos >> 2, c8 = (pos & 3) * 8;
        int gn = bn + r;
        b_sz[q]  = (gn < N) ? 16u : 0u;
        b_off[q] = (long)((gn < N) ? gn : 0) * H_SZ + c8;
        b_s[q] = (uint32_t)(r * 80 + (pos & 3) * 16);
    }

    float acc[4][8][4];
#pragma unroll
    for (int m = 0; m < 4; m++)
#pragma unroll
        for (int j = 0; j < 8; j++)
#pragma unroll
            for (int q = 0; q < 4; q++) acc[m][j][q] = 0.f;

#define G2_LOAD(ck, s) do {                                                   \
    const long ko = (long)(ck) * 32;                                          \
    const uint32_t st = sb + (s) * STG;                                       \
    _Pragma("unroll")                                                         \
    for (int q = 0; q < 2; q++) {                                             \
        cp16(st + a_s[q], Ah + a_off[q] + ko, 16u);                           \
        if (APASS == 2) cp16(st + 10240 + a_s[q], Al + a_off[q] + ko, 16u);   \
    }                                                                         \
    _Pragma("unroll")                                                         \
    for (int q = 0; q < 4; q++)                                               \
        cp16(st + BOFF + b_s[q], Bh + b_off[q] + ko, b_sz[q]);                \
} while (0)

    G2_LOAD(0, 0); CP_COMMIT();
    G2_LOAD(1, 1); CP_COMMIT();

    for (int ck = 0; ck < 32; ck++) {
        const int s = ck & 1;
        CP_WAIT1();
        __syncthreads();
        const uint32_t sA = sb + s * STG;
        const uint32_t sB = sA + BOFF;
#pragma unroll
        for (int ks = 0; ks < 2; ks++) {
            uint32_t ah[4][4], al[4][4], bh[16];
            const int arow = lane & 15;
            const uint32_t ac = (uint32_t)(((lane >> 4) * 8 + ks * 16) * 2);
#pragma unroll
            for (int mf = 0; mf < 4; mf++) {
                uint32_t ad = sA + (uint32_t)((wm + mf * 16 + arow) * 80) + ac;
                ldsm4(ah[mf], ad);
                if (APASS == 2) ldsm4(al[mf], ad + 10240);
            }
            const int brow = (lane & 7) + ((lane >> 4) & 1) * 8;
            const uint32_t bcd = (uint32_t)(((((lane >> 3) & 1) * 8) + ks * 16) * 2);
#pragma unroll
            for (int pf = 0; pf < 4; pf++) {
                uint32_t bd = sB + (uint32_t)((wn + pf * 16 + brow) * 80) + bcd;
                ldsm4(&bh[pf * 4], bd);
            }
#pragma unroll
            for (int m = 0; m < 4; m++)
#pragma unroll
                for (int j = 0; j < 8; j++) {
                    const int bi = (j >> 1) * 4 + (j & 1) * 2;
                    mma_f16(acc[m][j], ah[m], bh[bi], bh[bi + 1]);
                    if (APASS == 2) mma_f16(acc[m][j], al[m], bh[bi], bh[bi + 1]);
                }
        }
        __syncthreads();
        if (ck + 2 < 32) G2_LOAD(ck + 2, s);
        CP_COMMIT();
    }

#pragma unroll
    for (int m = 0; m < 4; m++) {
        const int r0 = bm + wm + m * 16 + (lane >> 2);
#pragma unroll
        for (int j = 0; j < 8; j++) {
            const int col = bn + wn + j * 8 + (lane & 3) * 2;
#pragma unroll
            for (int hh = 0; hh < 2; hh++) {
                const int r = r0 + hh * 8;
                if (col < N)     C[(size_t)r * N + col]     = acc[m][j][hh * 2 + 0] + bias[col];
                if (col + 1 < N) C[(size_t)r * N + col + 1] = acc[m][j][hh * 2 + 1] + bias[col + 1];
            }
        }
    }
#undef G2_LOAD
}

// ===================== fused LSTM step (fp16x2 mma.sync) =====================
__global__ __launch_bounds__(128, 1)
void lstm_step_mma(const __half* __restrict__ WhT16,
                   const __half* __restrict__ hh,
                   const __half* __restrict__ hl,
                   const float* __restrict__ px_t,
                   __half* __restrict__ oh, __half* __restrict__ ol,
                   float* __restrict__ hf, float* __restrict__ cf, int last)
{
    __shared__ __align__(16) char smem[25600];
    const uint32_t sb = smem_u32(smem);
    const int tid = threadIdx.x, lane = tid & 31, wid = tid >> 5;
    const int u0 = blockIdx.x * 8;
    const int wm = (wid >> 1) * 16, wn = (wid & 1) * 32;

    long a_off;
    uint32_t a_s;
    {
        int r = tid >> 2, c8 = (tid & 3) * 8;
        long grow = (long)(r >> 3) * H_SZ + u0 + (r & 7);
        a_off = grow * H_SZ + c8;
        a_s = (uint32_t)(r * 80 + (tid & 3) * 16);
    }
    long b_off[2];
    uint32_t b_s[2];
#pragma unroll
    for (int q = 0; q < 2; q++) {
        int pos = q * 128 + tid;
        int r = pos >> 2, c8 = (pos & 3) * 8;
        b_off[q] = (long)r * H_SZ + c8;
        b_s[q] = (uint32_t)(r * 80 + (pos & 3) * 16);
    }

    float acc[4][4];
#pragma unroll
    for (int j = 0; j < 4; j++)
#pragma unroll
        for (int q = 0; q < 4; q++) acc[j][q] = 0.f;

#define S_LOAD(ck, s) do {                                                    \
    const long ko = (long)(ck) * 32;                                          \
    const uint32_t st = sb + (s) * 12800;                                     \
    cp16(st + a_s, WhT16 + a_off + ko, 16u);                                  \
    _Pragma("unroll")                                                         \
    for (int q = 0; q < 2; q++) {                                             \
        cp16(st + 2560 + b_s[q], hh + b_off[q] + ko, 16u);                    \
        cp16(st + 7680 + b_s[q], hl + b_off[q] + ko, 16u);                    \
    }                                                                         \
} while (0)

    S_LOAD(0, 0); CP_COMMIT();
    S_LOAD(1, 1); CP_COMMIT();

    for (int ck = 0; ck < 32; ck++) {
        const int s = ck & 1;
        CP_WAIT1();
        __syncthreads();
        const uint32_t sA = sb + s * 12800;
        const uint32_t sB = sA + 2560;
#pragma unroll
        for (int ks = 0; ks < 2; ks++) {
            uint32_t ah[4], bh[8], bl[8];
            const uint32_t ac = (uint32_t)(((lane >> 4) * 8 + ks * 16) * 2);
            {
                uint32_t ad = sA + (uint32_t)((wm + (lane & 15)) * 80) + ac;
                ldsm4(ah, ad);
            }
            const int brow = (lane & 7) + ((lane >> 4) & 1) * 8;
            const uint32_t bcd = (uint32_t)(((((lane >> 3) & 1) * 8) + ks * 16) * 2);
#pragma unroll
            for (int pf = 0; pf < 2; pf++) {
                uint32_t bd = sB + (uint32_t)((wn + pf * 16 + brow) * 80) + bcd;
                ldsm4(&bh[pf * 4], bd);
                ldsm4(&bl[pf * 4], bd + 5120);
            }
#pragma unroll
            for (int j = 0; j < 4; j++) {
                const int bi = (j >> 1) * 4 + (j & 1) * 2;
                mma_f16(acc[j], ah, bh[bi], bh[bi + 1]);
                mma_f16(acc[j], ah, bl[bi], bl[bi + 1]);
            }
        }
        __syncthreads();
        if (ck + 2 < 32) S_LOAD(ck + 2, s);
        CP_COMMIT();
    }

    __syncthreads();
    float* Gs = (float*)smem;   // [32][65]
    {
        const int row = wm + (lane >> 2);
#pragma unroll
        for (int j = 0; j < 4; j++) {
            const int col = wn + j * 8 + (lane & 3) * 2;
            Gs[row * 65 + col]           = acc[j][0];
            Gs[row * 65 + col + 1]       = acc[j][1];
            Gs[(row + 8) * 65 + col]     = acc[j][2];
            Gs[(row + 8) * 65 + col + 1] = acc[j][3];
        }
    }
    __syncthreads();

    {
        const int u = tid & 7;
        const int b0 = (tid >> 3) * 4;
        const int gu = u0 + u;
#pragma unroll
        for (int jj = 0; jj < 4; jj++) {
            const int b = b0 + jj;
            const float* pxb = px_t + (size_t)b * H4;
            float gi = Gs[(0 * 8 + u) * 65 + b] + pxb[gu];
            float gf = Gs[(1 * 8 + u) * 65 + b] + pxb[1024 + gu];
            float gg = Gs[(2 * 8 + u) * 65 + b] + pxb[2048 + gu];
            float go = Gs[(3 * 8 + u) * 65 + b] + pxb[3072 + gu];
            float si = 1.f / (1.f + expf(-gi));
            float sf = 1.f / (1.f + expf(-gf));
            float so = 1.f / (1.f + expf(-go));
            float tg = tanhf(gg);
            const int ci = b * H_SZ + gu;
            float cn = sf * g_c[ci] + si * tg;
            float hn = so * tanhf(cn);
            g_c[ci] = cn;
            __half vh, vl;
            split_h16(hn, vh, vl);
            oh[ci] = vh; ol[ci] = vl;
            if (last) { hf[ci] = hn; cf[ci] = cn; }
        }
    }
#undef S_LOAD
}

// ===================== launch ================================================
extern "C" void kernel_launch(void* const* d_in, const int* in_sizes, int n_in,
                              void* d_out, int out_size)
{
    const int*   x      = (const int*)  d_in[0];
    const float* h      = (const float*)d_in[1];
    const float* c      = (const float*)d_in[2];
    const float* emb    = (const float*)d_in[3];
    const float* W_proj = (const float*)d_in[4];
    const float* b_proj = (const float*)d_in[5];
    const float* W_x    = (const float*)d_in[6];
    const float* W_h    = (const float*)d_in[7];
    const float* b_lstm = (const float*)d_in[8];
    const float* W_out  = (const float*)d_in[9];
    const float* b_out  = (const float*)d_in[10];
    float* out = (float*)d_out;

    float *px, *cbuf, *bc;
    __nv_bfloat16 *wxth, *wxtl, *wph, *wpl;
    __half *r16h, *r16l, *e16h, *wht16, *wot16, *wct16;
    cudaGetSymbolAddress((void**)&px,    g_px);
    cudaGetSymbolAddress((void**)&cbuf,  g_c);
    cudaGetSymbolAddress((void**)&bc,    g_bc);
    cudaGetSymbolAddress((void**)&r16h,  g_res16h);
    cudaGetSymbolAddress((void**)&r16l,  g_res16l);
    cudaGetSymbolAddress((void**)&e16h,  g_emb16h);
    cudaGetSymbolAddress((void**)&wxth,  g_WxT_hi);
    cudaGetSymbolAddress((void**)&wxtl,  g_WxT_lo);
    cudaGetSymbolAddress((void**)&wht16, g_WhT16);
    cudaGetSymbolAddress((void**)&wot16, g_WoT16);
    cudaGetSymbolAddress((void**)&wph,   g_Wp_hi);
    cudaGetSymbolAddress((void**)&wpl,   g_Wp_lo);
    cudaGetSymbolAddress((void**)&wct16, g_WcT16);

    cudaFuncSetAttribute(mma_gemm_bf16,
                         cudaFuncAttributeMaxDynamicSharedMemorySize, G_SMEM_BYTES);
    cudaFuncSetAttribute(mma_gemm_f16<true, 1>,
                         cudaFuncAttributeMaxDynamicSharedMemorySize, 2 * 30720);
    cudaFuncSetAttribute(mma_gemm_f16<false, 1>,
                         cudaFuncAttributeMaxDynamicSharedMemorySize, 2 * 30720);

    // ---------- prepass on stream 0 ----------
    cudaMemcpyAsync(cbuf, c, (size_t)BH * sizeof(float),
                    cudaMemcpyDeviceToDevice, 0);
    split_kernel<<<512, 256>>>(W_proj, wph, wpl, (long)H_SZ * H_SZ);
    conv16_kernel<<<2048, 256>>>(emb, e16h, (long)O_SZ * H_SZ);
    split16_kernel<<<64, 256>>>(h, r16h, r16l, (long)BH);   // slab 0 = h_{-1}
    transpose_split_kernel<<<dim3(H4 / 32, H_SZ / 32), 256>>>(W_x, wxth, wxtl, H_SZ, H4);
    transpose16_kernel<<<dim3(H4 / 32, H_SZ / 32), 256>>>(W_h, wht16, H_SZ, H4);
    transpose16_kernel<<<dim3((O_SZ + 31) / 32, H_SZ / 32), 256>>>(W_out, wot16, H_SZ, O_SZ);
    bc_kernel<<<(H4 + 255) / 256, 256>>>(b_proj, W_x, b_lstm, bc);

    cudaEventRecord(g_evPre, 0);
    cudaStreamWaitEvent(g_s1, g_evPre, 0);
    cudaStreamWaitEvent(g_s2, g_evPre, 0);

    // ---------- Wc + px chunks on s1 (low priority) ----------
    mma_gemm_bf16<<<dim3(H_SZ / 128, H4 / 128), 256, G_SMEM_BYTES, g_s1>>>(
        wxth, wxtl, wph, wpl, wct16, H4, H_SZ);

    for (int k = 0; k < N_CHUNK; k++) {
        const int rows = T_PER_CHUNK * B_SZ;   // 1024
        mma_gemm_f16<true, 1><<<dim3(H4 / 256, rows / 128), 256, 2 * 30720, g_s1>>>(
            e16h, nullptr, wct16, x + (size_t)k * rows, bc,
            px + (size_t)k * rows * H4, rows, H4);
        cudaEventRecord(g_evPx[k], g_s1);
    }

    // ---------- sequential LSTM scan on s2 (high priority) ----------
    float* hf_out = out + (size_t)TB * O_SZ;
    float* cf_out = hf_out + BH;
    for (int t = 0; t < T_STEPS; t++) {
        if ((t % T_PER_CHUNK) == 0)
            cudaStreamWaitEvent(g_s2, g_evPx[t / T_PER_CHUNK], 0);
        lstm_step_mma<<<128, 128, 0, g_s2>>>(
            wht16,
            r16h + (size_t)t * BH, r16l + (size_t)t * BH,
            px + (size_t)t * B_SZ * H4,
            r16h + (size_t)(t + 1) * BH, r16l + (size_t)(t + 1) * BH,
            hf_out, cf_out, (t == T_STEPS - 1) ? 1 : 0);
        if ((t % T_PER_CHUNK) == T_PER_CHUNK - 1)
            cudaEventRecord(g_evScan[t / T_PER_CHUNK], g_s2);
    }
    cudaEventRecord(g_evDone2, g_s2);

    // ---------- out chunks on s1, overlapping the scan ----------
    for (int k = 0; k < N_CHUNK; k++) {
        const int rows = T_PER_CHUNK * B_SZ;   // 1024
        cudaStreamWaitEvent(g_s1, g_evScan[k], 0);
        mma_gemm_f16<false, 1><<<dim3((O_SZ + 255) / 256, rows / 128), 256, 2 * 30720, g_s1>>>(
            r16h + BH + (size_t)k * rows * H_SZ, nullptr,
            wot16, nullptr, b_out,
            out + (size_t)k * rows * O_SZ, rows, O_SZ);
    }

    cudaEventRecord(g_evDone1, g_s1);
    cudaStreamWaitEvent(0, g_evDone1, 0);
    cudaStreamWaitEvent(0, g_evDone2, 0);
}

// round 8
// speedup vs baseline: 3.1255x; 1.0213x over previous
#include <cuda_runtime.h>
#include <cuda_bf16.h>
#include <cuda_fp16.h>
#include <cstdint>
#include <math.h>

#define T_STEPS 256
#define B_SZ 64
#define H_SZ 1024
#define H4 4096
#define O_SZ 10000
#define TB (T_STEPS * B_SZ)
#define BH (B_SZ * H_SZ)
#define N_CHUNK 16
#define T_PER_CHUNK (T_STEPS / N_CHUNK)

// ===================== low-level helpers (sm_80+ features only) =============
__device__ __forceinline__ uint32_t smem_u32(const void* p) {
    uint32_t a;
    asm("{ .reg .u64 t; cvta.to.shared.u64 t, %1; cvt.u32.u64 %0, t; }"
        : "=r"(a) : "l"(p));
    return a;
}
__device__ __forceinline__ void ldsm4(uint32_t* r, uint32_t a) {
    asm volatile("ldmatrix.sync.aligned.m8n8.x4.shared.b16 {%0,%1,%2,%3}, [%4];"
                 : "=r"(r[0]), "=r"(r[1]), "=r"(r[2]), "=r"(r[3]) : "r"(a));
}
__device__ __forceinline__ void mma_bf16(float* c, const uint32_t* a,
                                         uint32_t b0, uint32_t b1) {
    asm volatile(
        "mma.sync.aligned.m16n8k16.row.col.f32.bf16.bf16.f32 "
        "{%0,%1,%2,%3}, {%4,%5,%6,%7}, {%8,%9}, {%0,%1,%2,%3};"
        : "+f"(c[0]), "+f"(c[1]), "+f"(c[2]), "+f"(c[3])
        : "r"(a[0]), "r"(a[1]), "r"(a[2]), "r"(a[3]), "r"(b0), "r"(b1));
}
__device__ __forceinline__ void mma_f16(float* c, const uint32_t* a,
                                        uint32_t b0, uint32_t b1) {
    asm volatile(
        "mma.sync.aligned.m16n8k16.row.col.f32.f16.f16.f32 "
        "{%0,%1,%2,%3}, {%4,%5,%6,%7}, {%8,%9}, {%0,%1,%2,%3};"
        : "+f"(c[0]), "+f"(c[1]), "+f"(c[2]), "+f"(c[3])
        : "r"(a[0]), "r"(a[1]), "r"(a[2]), "r"(a[3]), "r"(b0), "r"(b1));
}
__device__ __forceinline__ void cp16(uint32_t dst, const void* src, uint32_t sz) {
    asm volatile("cp.async.cg.shared.global [%0], [%1], 16, %2;"
                 :: "r"(dst), "l"(src), "r"(sz) : "memory");
}
#define CP_COMMIT() asm volatile("cp.async.commit_group;" ::: "memory")
#define CP_WAIT1()  asm volatile("cp.async.wait_group 1;" ::: "memory")
#define CP_WAIT2()  asm volatile("cp.async.wait_group 2;" ::: "memory")

__device__ __forceinline__ void split_bf(float x, __nv_bfloat16& hi, __nv_bfloat16& lo) {
    hi = __float2bfloat16(x);
    lo = __float2bfloat16(x - __bfloat162float(hi));
}

// ===================== scratch (device globals) ==============================
__device__ float          g_px[(size_t)TB * H4];
__device__ float          g_c[BH];
__device__ float          g_bc[H4];
__device__ __half         g_res16h[(size_t)(T_STEPS + 1) * BH];
__device__ __half         g_emb16h[(size_t)O_SZ * H_SZ];
__device__ __nv_bfloat16  g_WxT_hi[(size_t)H4 * H_SZ],   g_WxT_lo[(size_t)H4 * H_SZ];
__device__ __half         g_WhT16[(size_t)H4 * H_SZ];
__device__ __half         g_WoT16[(size_t)O_SZ * H_SZ];
__device__ __nv_bfloat16  g_Wp_hi[(size_t)H_SZ * H_SZ],  g_Wp_lo[(size_t)H_SZ * H_SZ];
__device__ __half         g_WcT16[(size_t)H4 * H_SZ];

// ===================== static streams/events (no device mem) ================
static cudaStream_t g_s1, g_s2;    // s1 = GEMMs (low prio), s2 = scan (high prio)
static cudaEvent_t  g_evPre, g_evDone1, g_evDone2;
static cudaEvent_t  g_evPx[N_CHUNK], g_evScan[N_CHUNK];
namespace {
struct StreamInit {
    StreamInit() {
        int lo, hi;
        cudaDeviceGetStreamPriorityRange(&lo, &hi);
        cudaStreamCreateWithPriority(&g_s1, cudaStreamNonBlocking, lo);
        cudaStreamCreateWithPriority(&g_s2, cudaStreamNonBlocking, hi);
        cudaEventCreateWithFlags(&g_evPre,   cudaEventDisableTiming);
        cudaEventCreateWithFlags(&g_evDone1, cudaEventDisableTiming);
        cudaEventCreateWithFlags(&g_evDone2, cudaEventDisableTiming);
        for (int i = 0; i < N_CHUNK; i++) {
            cudaEventCreateWithFlags(&g_evPx[i],   cudaEventDisableTiming);
            cudaEventCreateWithFlags(&g_evScan[i], cudaEventDisableTiming);
        }
    }
};
StreamInit g_streamInit;
}

// ===================== pre-pass kernels ======================================
__global__ void split_kernel(const float* __restrict__ in,
                             __nv_bfloat16* __restrict__ hi,
                             __nv_bfloat16* __restrict__ lo, long n) {
    long i = (long)blockIdx.x * blockDim.x + threadIdx.x;
    long stride = (long)gridDim.x * blockDim.x;
    for (; i < n; i += stride) split_bf(in[i], hi[i], lo[i]);
}
__global__ void conv16_kernel(const float* __restrict__ in,
                              __half* __restrict__ o, long n) {
    long i = (long)blockIdx.x * blockDim.x + threadIdx.x;
    long stride = (long)gridDim.x * blockDim.x;
    for (; i < n; i += stride) o[i] = __float2half(in[i]);
}
// [R x C] fp32 -> [C x R] bf16 hi/lo
__global__ void transpose_split_kernel(const float* __restrict__ in,
                                       __nv_bfloat16* __restrict__ hiT,
                                       __nv_bfloat16* __restrict__ loT,
                                       int R, int C) {
    __shared__ float ts[32][33];
    int c0 = blockIdx.x * 32, r0 = blockIdx.y * 32;
    int tx = threadIdx.x & 31, ty = threadIdx.x >> 5;
    for (int rr = ty; rr < 32; rr += 8) {
        int r = r0 + rr, c = c0 + tx;
        ts[rr][tx] = (r < R && c < C) ? in[(size_t)r * C + c] : 0.f;
    }
    __syncthreads();
    for (int cc = ty; cc < 32; cc += 8) {
        int c = c0 + cc, r = r0 + tx;
        if (c < C && r < R) {
            __nv_bfloat16 h, l;
            split_bf(ts[tx][cc], h, l);
            hiT[(size_t)c * R + r] = h;
            loT[(size_t)c * R + r] = l;
        }
    }
}
// [R x C] fp32 -> [C x R] fp16
__global__ void transpose16_kernel(const float* __restrict__ in,
                                   __half* __restrict__ hiT, int R, int C) {
    __shared__ float ts[32][33];
    int c0 = blockIdx.x * 32, r0 = blockIdx.y * 32;
    int tx = threadIdx.x & 31, ty = threadIdx.x >> 5;
    for (int rr = ty; rr < 32; rr += 8) {
        int r = r0 + rr, c = c0 + tx;
        ts[rr][tx] = (r < R && c < C) ? in[(size_t)r * C + c] : 0.f;
    }
    __syncthreads();
    for (int cc = ty; cc < 32; cc += 8) {
        int c = c0 + cc, r = r0 + tx;
        if (c < C && r < R) hiT[(size_t)c * R + r] = __float2half(ts[tx][cc]);
    }
}
__global__ void bc_kernel(const float* __restrict__ b_proj,
                          const float* __restrict__ W_x,
                          const float* __restrict__ b_lstm,
                          float* __restrict__ bc) {
    int n = blockIdx.x * blockDim.x + threadIdx.x;
    if (n >= H4) return;
    float s = b_lstm[n];
    for (int k = 0; k < H_SZ; k++) s += b_proj[k] * W_x[(size_t)k * H4 + n];
    bc[n] = s;
}

// ===================== bf16x3 GEMM (128x128) — Wc only ======================
#define G_SMEM_BYTES (2 * 40960)
__global__ __launch_bounds__(256, 1)
void mma_gemm_bf16(const __nv_bfloat16* __restrict__ Ah, const __nv_bfloat16* __restrict__ Al,
                   const __nv_bfloat16* __restrict__ Bh, const __nv_bfloat16* __restrict__ Bl,
                   __half* __restrict__ C16, int M, int N)
{
    extern __shared__ __align__(16) char smem[];
    const uint32_t sb = smem_u32(smem);
    const int tid = threadIdx.x, lane = tid & 31, wid = tid >> 5;
    const int bm = blockIdx.y * 128, bn = blockIdx.x * 128;
    const int wm = (wid >> 2) * 64, wn = (wid & 3) * 32;

    long a_off[2], b_off[2];
    uint32_t a_s[2], b_s[2], b_sz[2];
#pragma unroll
    for (int q = 0; q < 2; q++) {
        int pos = q * 256 + tid;
        int r = pos >> 2, c8 = (pos & 3) * 8;
        a_off[q] = (long)(bm + r) * H_SZ + c8;
        a_s[q] = (uint32_t)(r * 80 + (pos & 3) * 16);
        int gn = bn + r;
        b_sz[q]  = (gn < N) ? 16u : 0u;
        b_off[q] = (long)((gn < N) ? gn : 0) * H_SZ + c8;
        b_s[q] = a_s[q];
    }

    float acc[4][4][4];
#pragma unroll
    for (int m = 0; m < 4; m++)
#pragma unroll
        for (int j = 0; j < 4; j++)
#pragma unroll
            for (int q = 0; q < 4; q++) acc[m][j][q] = 0.f;

#define GB_LOAD(ck, s) do {                                                   \
    const long ko = (long)(ck) * 32;                                          \
    const uint32_t st = sb + (s) * 40960;                                     \
    _Pragma("unroll")                                                         \
    for (int q = 0; q < 2; q++) {                                             \
        cp16(st + a_s[q],         Ah + a_off[q] + ko, 16u);                   \
        cp16(st + 10240 + a_s[q], Al + a_off[q] + ko, 16u);                   \
        cp16(st + 20480 + b_s[q], Bh + b_off[q] + ko, b_sz[q]);               \
        cp16(st + 30720 + b_s[q], Bl + b_off[q] + ko, b_sz[q]);               \
    }                                                                         \
} while (0)

    GB_LOAD(0, 0); CP_COMMIT();
    GB_LOAD(1, 1); CP_COMMIT();

    for (int ck = 0; ck < 32; ck++) {
        const int s = ck & 1;
        CP_WAIT1();
        __syncthreads();
        const uint32_t sA = sb + s * 40960;
        const uint32_t sB = sA + 20480;
#pragma unroll
        for (int ks = 0; ks < 2; ks++) {
            uint32_t ah[4][4], al[4][4], bh[8], bl[8];
            const int arow = lane & 15;
            const uint32_t ac = (uint32_t)(((lane >> 4) * 8 + ks * 16) * 2);
#pragma unroll
            for (int mf = 0; mf < 4; mf++) {
                uint32_t ad = sA + (uint32_t)((wm + mf * 16 + arow) * 80) + ac;
                ldsm4(ah[mf], ad);
                ldsm4(al[mf], ad + 10240);
            }
            const int brow = (lane & 7) + ((lane >> 4) & 1) * 8;
            const uint32_t bcd = (uint32_t)(((((lane >> 3) & 1) * 8) + ks * 16) * 2);
#pragma unroll
            for (int pf = 0; pf < 2; pf++) {
                uint32_t bd = sB + (uint32_t)((wn + pf * 16 + brow) * 80) + bcd;
                ldsm4(&bh[pf * 4], bd);
                ldsm4(&bl[pf * 4], bd + 10240);
            }
#pragma unroll
            for (int m = 0; m < 4; m++)
#pragma unroll
                for (int j = 0; j < 4; j++) {
                    const int bi = (j >> 1) * 4 + (j & 1) * 2;
                    mma_bf16(acc[m][j], ah[m], bh[bi], bh[bi + 1]);
                    mma_bf16(acc[m][j], al[m], bh[bi], bh[bi + 1]);
                    mma_bf16(acc[m][j], ah[m], bl[bi], bl[bi + 1]);
                }
        }
        __syncthreads();
        if (ck + 2 < 32) GB_LOAD(ck + 2, s);
        CP_COMMIT();
    }

#pragma unroll
    for (int m = 0; m < 4; m++) {
        const int r0 = bm + wm + m * 16 + (lane >> 2);
#pragma unroll
        for (int j = 0; j < 4; j++) {
            const int col = bn + wn + j * 8 + (lane & 3) * 2;
#pragma unroll
            for (int hh = 0; hh < 2; hh++) {
                const int r = r0 + hh * 8;
                if (col < N)     C16[(size_t)r * N + col]     = __float2half(acc[m][j][hh * 2 + 0]);
                if (col + 1 < N) C16[(size_t)r * N + col + 1] = __float2half(acc[m][j][hh * 2 + 1]);
            }
        }
    }
#undef GB_LOAD
}

// ===================== fp16 GEMM (128x256), single A-pass ===================
// C[M,N] = Ah[M,1024] @ Bh[N,1024]^T + bias.  8 warps 2x4, warp 64x64.
// Stage: A 0 (10240), B 10240 (20480); stage 30720, 2 stages.
template <bool GATHER>
__global__ __launch_bounds__(256, 1)
void mma_gemm_f16(const __half* __restrict__ Ah,
                  const __half* __restrict__ Bh,
                  const int* __restrict__ gidx, const float* __restrict__ bias,
                  float* __restrict__ C, int M, int N)
{
    extern __shared__ __align__(16) char smem[];
    const uint32_t sb = smem_u32(smem);
    const int tid = threadIdx.x, lane = tid & 31, wid = tid >> 5;
    const int bm = blockIdx.y * 128, bn = blockIdx.x * 256;
    const int wm = (wid >> 2) * 64, wn = (wid & 3) * 64;

    long a_off[2];
    uint32_t a_s[2];
#pragma unroll
    for (int q = 0; q < 2; q++) {
        int pos = q * 256 + tid;
        int r = pos >> 2, c8 = (pos & 3) * 8;
        long ar = GATHER ? (long)gidx[bm + r] : (long)(bm + r);
        a_off[q] = ar * H_SZ + c8;
        a_s[q] = (uint32_t)(r * 80 + (pos & 3) * 16);
    }
    long b_off[4];
    uint32_t b_s[4], b_sz[4];
#pragma unroll
    for (int q = 0; q < 4; q++) {
        int pos = q * 256 + tid;
        int r = pos >> 2, c8 = (pos & 3) * 8;
        int gn = bn + r;
        b_sz[q]  = (gn < N) ? 16u : 0u;
        b_off[q] = (long)((gn < N) ? gn : 0) * H_SZ + c8;
        b_s[q] = (uint32_t)(r * 80 + (pos & 3) * 16);
    }

    float acc[4][8][4];
#pragma unroll
    for (int m = 0; m < 4; m++)
#pragma unroll
        for (int j = 0; j < 8; j++)
#pragma unroll
            for (int q = 0; q < 4; q++) acc[m][j][q] = 0.f;

#define G2_LOAD(ck, s) do {                                                   \
    const long ko = (long)(ck) * 32;                                          \
    const uint32_t st = sb + (s) * 30720;                                     \
    _Pragma("unroll")                                                         \
    for (int q = 0; q < 2; q++)                                               \
        cp16(st + a_s[q], Ah + a_off[q] + ko, 16u);                           \
    _Pragma("unroll")                                                         \
    for (int q = 0; q < 4; q++)                                               \
        cp16(st + 10240 + b_s[q], Bh + b_off[q] + ko, b_sz[q]);               \
} while (0)

    G2_LOAD(0, 0); CP_COMMIT();
    G2_LOAD(1, 1); CP_COMMIT();

    for (int ck = 0; ck < 32; ck++) {
        const int s = ck & 1;
        CP_WAIT1();
        __syncthreads();
        const uint32_t sA = sb + s * 30720;
        const uint32_t sB = sA + 10240;
#pragma unroll
        for (int ks = 0; ks < 2; ks++) {
            uint32_t ah[4][4], bh[16];
            const int arow = lane & 15;
            const uint32_t ac = (uint32_t)(((lane >> 4) * 8 + ks * 16) * 2);
#pragma unroll
            for (int mf = 0; mf < 4; mf++) {
                uint32_t ad = sA + (uint32_t)((wm + mf * 16 + arow) * 80) + ac;
                ldsm4(ah[mf], ad);
            }
            const int brow = (lane & 7) + ((lane >> 4) & 1) * 8;
            const uint32_t bcd = (uint32_t)(((((lane >> 3) & 1) * 8) + ks * 16) * 2);
#pragma unroll
            for (int pf = 0; pf < 4; pf++) {
                uint32_t bd = sB + (uint32_t)((wn + pf * 16 + brow) * 80) + bcd;
                ldsm4(&bh[pf * 4], bd);
            }
#pragma unroll
            for (int m = 0; m < 4; m++)
#pragma unroll
                for (int j = 0; j < 8; j++) {
                    const int bi = (j >> 1) * 4 + (j & 1) * 2;
                    mma_f16(acc[m][j], ah[m], bh[bi], bh[bi + 1]);
                }
        }
        __syncthreads();
        if (ck + 2 < 32) G2_LOAD(ck + 2, s);
        CP_COMMIT();
    }

#pragma unroll
    for (int m = 0; m < 4; m++) {
        const int r0 = bm + wm + m * 16 + (lane >> 2);
#pragma unroll
        for (int j = 0; j < 8; j++) {
            const int col = bn + wn + j * 8 + (lane & 3) * 2;
#pragma unroll
            for (int hh = 0; hh < 2; hh++) {
                const int r = r0 + hh * 8;
                if (col < N)     C[(size_t)r * N + col]     = acc[m][j][hh * 2 + 0] + bias[col];
                if (col + 1 < N) C[(size_t)r * N + col + 1] = acc[m][j][hh * 2 + 1] + bias[col + 1];
            }
        }
    }
#undef G2_LOAD
}

// ===================== fused LSTM step (fp16 single-pass, 4-stage) ==========
// CTA = 8 units x 4 gates (M=32) x 64 batch, K=1024. 4 warps 2x2, warp 16x32.
// h is fp16 single (hi only). Stage: A 0 (2560), B 2560 (5120); stage 7680, x4.
#define S_STG 7680
__global__ __launch_bounds__(128, 1)
void lstm_step_mma(const __half* __restrict__ WhT16,
                   const __half* __restrict__ hh,
                   const float* __restrict__ px_t,
                   __half* __restrict__ oh,
                   float* __restrict__ hf, float* __restrict__ cf, int last)
{
    __shared__ __align__(16) char smem[4 * S_STG];   // 30720 B
    const uint32_t sb = smem_u32(smem);
    const int tid = threadIdx.x, lane = tid & 31, wid = tid >> 5;
    const int u0 = blockIdx.x * 8;
    const int wm = (wid >> 1) * 16, wn = (wid & 1) * 32;

    long a_off;
    uint32_t a_s;
    {
        int r = tid >> 2, c8 = (tid & 3) * 8;     // r: 0..31
        long grow = (long)(r >> 3) * H_SZ + u0 + (r & 7);
        a_off = grow * H_SZ + c8;
        a_s = (uint32_t)(r * 80 + (tid & 3) * 16);
    }
    long b_off[2];
    uint32_t b_s[2];
#pragma unroll
    for (int q = 0; q < 2; q++) {
        int pos = q * 128 + tid;
        int r = pos >> 2, c8 = (pos & 3) * 8;     // r: 0..63
        b_off[q] = (long)r * H_SZ + c8;
        b_s[q] = (uint32_t)(r * 80 + (pos & 3) * 16);
    }

    float acc[4][4];
#pragma unroll
    for (int j = 0; j < 4; j++)
#pragma unroll
        for (int q = 0; q < 4; q++) acc[j][q] = 0.f;

#define S_LOAD(ck, s) do {                                                    \
    const long ko = (long)(ck) * 32;                                          \
    const uint32_t st = sb + (s) * S_STG;                                     \
    cp16(st + a_s, WhT16 + a_off + ko, 16u);                                  \
    _Pragma("unroll")                                                         \
    for (int q = 0; q < 2; q++)                                               \
        cp16(st + 2560 + b_s[q], hh + b_off[q] + ko, 16u);                    \
} while (0)

    // prefetch stages 0..2
    S_LOAD(0, 0); CP_COMMIT();
    S_LOAD(1, 1); CP_COMMIT();
    S_LOAD(2, 2); CP_COMMIT();

    for (int ck = 0; ck < 32; ck++) {
        const int s = ck & 3;
        CP_WAIT2();          // stage ck's group complete (<=2 newer pending)
        __syncthreads();
        const uint32_t sA = sb + s * S_STG;
        const uint32_t sB = sA + 2560;
#pragma unroll
        for (int ks = 0; ks < 2; ks++) {
            uint32_t ah[4], bh[8];
            const uint32_t ac = (uint32_t)(((lane >> 4) * 8 + ks * 16) * 2);
            {
                uint32_t ad = sA + (uint32_t)((wm + (lane & 15)) * 80) + ac;
                ldsm4(ah, ad);
            }
            const int brow = (lane & 7) + ((lane >> 4) & 1) * 8;
            const uint32_t bcd = (uint32_t)(((((lane >> 3) & 1) * 8) + ks * 16) * 2);
#pragma unroll
            for (int pf = 0; pf < 2; pf++) {
                uint32_t bd = sB + (uint32_t)((wn + pf * 16 + brow) * 80) + bcd;
                ldsm4(&bh[pf * 4], bd);
            }
#pragma unroll
            for (int j = 0; j < 4; j++) {
                const int bi = (j >> 1) * 4 + (j & 1) * 2;
                mma_f16(acc[j], ah, bh[bi], bh[bi + 1]);
            }
        }
        // load target stage (ck+3)&3 == (ck-1)&3: fully consumed at iter ck-1,
        // and all threads passed this iter's top barrier -> no WAR hazard.
        if (ck + 3 < 32) S_LOAD(ck + 3, (ck + 3) & 3);
        CP_COMMIT();
    }

    __syncthreads();
    float* Gs = (float*)smem;   // [32][65] fp32 gate exchange (8320 B)
    {
        const int row = wm + (lane >> 2);
#pragma unroll
        for (int j = 0; j < 4; j++) {
            const int col = wn + j * 8 + (lane & 3) * 2;
            Gs[row * 65 + col]           = acc[j][0];
            Gs[row * 65 + col + 1]       = acc[j][1];
            Gs[(row + 8) * 65 + col]     = acc[j][2];
            Gs[(row + 8) * 65 + col + 1] = acc[j][3];
        }
    }
    __syncthreads();

    {
        const int u = tid & 7;
        const int b0 = (tid >> 3) * 4;
        const int gu = u0 + u;
#pragma unroll
        for (int jj = 0; jj < 4; jj++) {
            const int b = b0 + jj;
            const float* pxb = px_t + (size_t)b * H4;
            float gi = Gs[(0 * 8 + u) * 65 + b] + pxb[gu];
            float gf = Gs[(1 * 8 + u) * 65 + b] + pxb[1024 + gu];
            float gg = Gs[(2 * 8 + u) * 65 + b] + pxb[2048 + gu];
            float go = Gs[(3 * 8 + u) * 65 + b] + pxb[3072 + gu];
            float si = 1.f / (1.f + expf(-gi));
            float sf = 1.f / (1.f + expf(-gf));
            float so = 1.f / (1.f + expf(-go));
            float tg = tanhf(gg);
            const int ci = b * H_SZ + gu;
            float cn = sf * g_c[ci] + si * tg;
            float hn = so * tanhf(cn);
            g_c[ci] = cn;
            oh[ci] = __float2half(hn);
            if (last) { hf[ci] = hn; cf[ci] = cn; }
        }
    }
#undef S_LOAD
}

// ===================== launch ================================================
extern "C" void kernel_launch(void* const* d_in, const int* in_sizes, int n_in,
                              void* d_out, int out_size)
{
    const int*   x      = (const int*)  d_in[0];
    const float* h      = (const float*)d_in[1];
    const float* c      = (const float*)d_in[2];
    const float* emb    = (const float*)d_in[3];
    const float* W_proj = (const float*)d_in[4];
    const float* b_proj = (const float*)d_in[5];
    const float* W_x    = (const float*)d_in[6];
    const float* W_h    = (const float*)d_in[7];
    const float* b_lstm = (const float*)d_in[8];
    const float* W_out  = (const float*)d_in[9];
    const float* b_out  = (const float*)d_in[10];
    float* out = (float*)d_out;

    float *px, *cbuf, *bc;
    __nv_bfloat16 *wxth, *wxtl, *wph, *wpl;
    __half *r16h, *e16h, *wht16, *wot16, *wct16;
    cudaGetSymbolAddress((void**)&px,    g_px);
    cudaGetSymbolAddress((void**)&cbuf,  g_c);
    cudaGetSymbolAddress((void**)&bc,    g_bc);
    cudaGetSymbolAddress((void**)&r16h,  g_res16h);
    cudaGetSymbolAddress((void**)&e16h,  g_emb16h);
    cudaGetSymbolAddress((void**)&wxth,  g_WxT_hi);
    cudaGetSymbolAddress((void**)&wxtl,  g_WxT_lo);
    cudaGetSymbolAddress((void**)&wht16, g_WhT16);
    cudaGetSymbolAddress((void**)&wot16, g_WoT16);
    cudaGetSymbolAddress((void**)&wph,   g_Wp_hi);
    cudaGetSymbolAddress((void**)&wpl,   g_Wp_lo);
    cudaGetSymbolAddress((void**)&wct16, g_WcT16);

    cudaFuncSetAttribute(mma_gemm_bf16,
                         cudaFuncAttributeMaxDynamicSharedMemorySize, G_SMEM_BYTES);
    cudaFuncSetAttribute(mma_gemm_f16<true>,
                         cudaFuncAttributeMaxDynamicSharedMemorySize, 2 * 30720);
    cudaFuncSetAttribute(mma_gemm_f16<false>,
                         cudaFuncAttributeMaxDynamicSharedMemorySize, 2 * 30720);

    // ---------- prepass on stream 0 ----------
    cudaMemcpyAsync(cbuf, c, (size_t)BH * sizeof(float),
                    cudaMemcpyDeviceToDevice, 0);
    split_kernel<<<512, 256>>>(W_proj, wph, wpl, (long)H_SZ * H_SZ);
    conv16_kernel<<<2048, 256>>>(emb, e16h, (long)O_SZ * H_SZ);
    conv16_kernel<<<64, 256>>>(h, r16h, (long)BH);   // slab 0 = h_{-1}
    transpose_split_kernel<<<dim3(H4 / 32, H_SZ / 32), 256>>>(W_x, wxth, wxtl, H_SZ, H4);
    transpose16_kernel<<<dim3(H4 / 32, H_SZ / 32), 256>>>(W_h, wht16, H_SZ, H4);
    transpose16_kernel<<<dim3((O_SZ + 31) / 32, H_SZ / 32), 256>>>(W_out, wot16, H_SZ, O_SZ);
    bc_kernel<<<(H4 + 255) / 256, 256>>>(b_proj, W_x, b_lstm, bc);

    cudaEventRecord(g_evPre, 0);
    cudaStreamWaitEvent(g_s1, g_evPre, 0);
    cudaStreamWaitEvent(g_s2, g_evPre, 0);

    // ---------- Wc + px chunks on s1 (low priority) ----------
    mma_gemm_bf16<<<dim3(H_SZ / 128, H4 / 128), 256, G_SMEM_BYTES, g_s1>>>(
        wxth, wxtl, wph, wpl, wct16, H4, H_SZ);

    for (int k = 0; k < N_CHUNK; k++) {
        const int rows = T_PER_CHUNK * B_SZ;   // 1024
        mma_gemm_f16<true><<<dim3(H4 / 256, rows / 128), 256, 2 * 30720, g_s1>>>(
            e16h, wct16, x + (size_t)k * rows, bc,
            px + (size_t)k * rows * H4, rows, H4);
        cudaEventRecord(g_evPx[k], g_s1);
    }

    // ---------- sequential LSTM scan on s2 (high priority) ----------
    float* hf_out = out + (size_t)TB * O_SZ;
    float* cf_out = hf_out + BH;
    for (int t = 0; t < T_STEPS; t++) {
        if ((t % T_PER_CHUNK) == 0)
            cudaStreamWaitEvent(g_s2, g_evPx[t / T_PER_CHUNK], 0);
        lstm_step_mma<<<128, 128, 0, g_s2>>>(
            wht16,
            r16h + (size_t)t * BH,
            px + (size_t)t * B_SZ * H4,
            r16h + (size_t)(t + 1) * BH,
            hf_out, cf_out, (t == T_STEPS - 1) ? 1 : 0);
        if ((t % T_PER_CHUNK) == T_PER_CHUNK - 1)
            cudaEventRecord(g_evScan[t / T_PER_CHUNK], g_s2);
    }
    cudaEventRecord(g_evDone2, g_s2);

    // ---------- out chunks on s1, overlapping the scan ----------
    for (int k = 0; k < N_CHUNK; k++) {
        const int rows = T_PER_CHUNK * B_SZ;   // 1024
        cudaStreamWaitEvent(g_s1, g_evScan[k], 0);
        mma_gemm_f16<false><<<dim3((O_SZ + 255) / 256, rows / 128), 256, 2 * 30720, g_s1>>>(
            r16h + BH + (size_t)k * rows * H_SZ,
            wot16, nullptr, b_out,
            out + (size_t)k * rows * O_SZ, rows, O_SZ);
    }

    cudaEventRecord(g_evDone1, g_s1);
    cudaStreamWaitEvent(0, g_evDone1, 0);
    cudaStreamWaitEvent(0, g_evDone2, 0);
}

// round 9
// speedup vs baseline: 4.7559x; 1.5217x over previous
#include <cuda_runtime.h>
#include <cuda_bf16.h>
#include <cuda_fp16.h>
#include <cstdint>
#include <math.h>

#define T_STEPS 256
#define B_SZ 64
#define H_SZ 1024
#define H4 4096
#define O_SZ 10000
#define TB (T_STEPS * B_SZ)
#define BH (B_SZ * H_SZ)

// ===================== low-level helpers (sm_80+ features only) =============
__device__ __forceinline__ uint32_t smem_u32(const void* p) {
    uint32_t a;
    asm("{ .reg .u64 t; cvta.to.shared.u64 t, %1; cvt.u32.u64 %0, t; }"
        : "=r"(a) : "l"(p));
    return a;
}
__device__ __forceinline__ void ldsm4(uint32_t* r, uint32_t a) {
    asm volatile("ldmatrix.sync.aligned.m8n8.x4.shared.b16 {%0,%1,%2,%3}, [%4];"
                 : "=r"(r[0]), "=r"(r[1]), "=r"(r[2]), "=r"(r[3]) : "r"(a));
}
__device__ __forceinline__ void mma_bf16(float* c, const uint32_t* a,
                                         uint32_t b0, uint32_t b1) {
    asm volatile(
        "mma.sync.aligned.m16n8k16.row.col.f32.bf16.bf16.f32 "
        "{%0,%1,%2,%3}, {%4,%5,%6,%7}, {%8,%9}, {%0,%1,%2,%3};"
        : "+f"(c[0]), "+f"(c[1]), "+f"(c[2]), "+f"(c[3])
        : "r"(a[0]), "r"(a[1]), "r"(a[2]), "r"(a[3]), "r"(b0), "r"(b1));
}
__device__ __forceinline__ void mma_f16(float* c, const uint32_t* a,
                                        uint32_t b0, uint32_t b1) {
    asm volatile(
        "mma.sync.aligned.m16n8k16.row.col.f32.f16.f16.f32 "
        "{%0,%1,%2,%3}, {%4,%5,%6,%7}, {%8,%9}, {%0,%1,%2,%3};"
        : "+f"(c[0]), "+f"(c[1]), "+f"(c[2]), "+f"(c[3])
        : "r"(a[0]), "r"(a[1]), "r"(a[2]), "r"(a[3]), "r"(b0), "r"(b1));
}
__device__ __forceinline__ void cp16(uint32_t dst, const void* src, uint32_t sz) {
    asm volatile("cp.async.cg.shared.global [%0], [%1], 16, %2;"
                 :: "r"(dst), "l"(src), "r"(sz) : "memory");
}
#define CP_COMMIT() asm volatile("cp.async.commit_group;" ::: "memory")
#define CP_WAIT0()  asm volatile("cp.async.wait_group 0;" ::: "memory")
#define CP_WAIT1()  asm volatile("cp.async.wait_group 1;" ::: "memory")
#define CP_WAIT2()  asm volatile("cp.async.wait_group 2;" ::: "memory")

__device__ __forceinline__ void split_bf(float x, __nv_bfloat16& hi, __nv_bfloat16& lo) {
    hi = __float2bfloat16(x);
    lo = __float2bfloat16(x - __bfloat162float(hi));
}

// ===================== scratch (device globals) ==============================
__device__ float          g_px[(size_t)TB * H4];
__device__ float          g_bc[H4];
__device__ unsigned int   g_bar;
__device__ __half         g_res16h[(size_t)(T_STEPS + 1) * BH];
__device__ __half         g_emb16h[(size_t)O_SZ * H_SZ];
__device__ __nv_bfloat16  g_WxT_hi[(size_t)H4 * H_SZ],   g_WxT_lo[(size_t)H4 * H_SZ];
__device__ __half         g_WhT16[(size_t)H4 * H_SZ];
__device__ __half         g_WoT16[(size_t)O_SZ * H_SZ];
__device__ __nv_bfloat16  g_Wp_hi[(size_t)H_SZ * H_SZ],  g_Wp_lo[(size_t)H_SZ * H_SZ];
__device__ __half         g_WcT16[(size_t)H4 * H_SZ];

// ===================== pre-pass kernels ======================================
__global__ void split_kernel(const float* __restrict__ in,
                             __nv_bfloat16* __restrict__ hi,
                             __nv_bfloat16* __restrict__ lo, long n) {
    long i = (long)blockIdx.x * blockDim.x + threadIdx.x;
    long stride = (long)gridDim.x * blockDim.x;
    for (; i < n; i += stride) split_bf(in[i], hi[i], lo[i]);
}
__global__ void conv16_kernel(const float* __restrict__ in,
                              __half* __restrict__ o, long n) {
    long i = (long)blockIdx.x * blockDim.x + threadIdx.x;
    long stride = (long)gridDim.x * blockDim.x;
    for (; i < n; i += stride) o[i] = __float2half(in[i]);
}
// [R x C] fp32 -> [C x R] bf16 hi/lo
__global__ void transpose_split_kernel(const float* __restrict__ in,
                                       __nv_bfloat16* __restrict__ hiT,
                                       __nv_bfloat16* __restrict__ loT,
                                       int R, int C) {
    __shared__ float ts[32][33];
    int c0 = blockIdx.x * 32, r0 = blockIdx.y * 32;
    int tx = threadIdx.x & 31, ty = threadIdx.x >> 5;
    for (int rr = ty; rr < 32; rr += 8) {
        int r = r0 + rr, c = c0 + tx;
        ts[rr][tx] = (r < R && c < C) ? in[(size_t)r * C + c] : 0.f;
    }
    __syncthreads();
    for (int cc = ty; cc < 32; cc += 8) {
        int c = c0 + cc, r = r0 + tx;
        if (c < C && r < R) {
            __nv_bfloat16 h, l;
            split_bf(ts[tx][cc], h, l);
            hiT[(size_t)c * R + r] = h;
            loT[(size_t)c * R + r] = l;
        }
    }
}
// [R x C] fp32 -> [C x R] fp16
__global__ void transpose16_kernel(const float* __restrict__ in,
                                   __half* __restrict__ hiT, int R, int C) {
    __shared__ float ts[32][33];
    int c0 = blockIdx.x * 32, r0 = blockIdx.y * 32;
    int tx = threadIdx.x & 31, ty = threadIdx.x >> 5;
    for (int rr = ty; rr < 32; rr += 8) {
        int r = r0 + rr, c = c0 + tx;
        ts[rr][tx] = (r < R && c < C) ? in[(size_t)r * C + c] : 0.f;
    }
    __syncthreads();
    for (int cc = ty; cc < 32; cc += 8) {
        int c = c0 + cc, r = r0 + tx;
        if (c < C && r < R) hiT[(size_t)c * R + r] = __float2half(ts[tx][cc]);
    }
}
__global__ void bc_kernel(const float* __restrict__ b_proj,
                          const float* __restrict__ W_x,
                          const float* __restrict__ b_lstm,
                          float* __restrict__ bc) {
    int n = blockIdx.x * blockDim.x + threadIdx.x;
    if (n >= H4) return;
    float s = b_lstm[n];
    for (int k = 0; k < H_SZ; k++) s += b_proj[k] * W_x[(size_t)k * H4 + n];
    bc[n] = s;
}

// ===================== bf16x3 GEMM (128x128) — Wc only ======================
#define G_SMEM_BYTES (2 * 40960)
__global__ __launch_bounds__(256, 1)
void mma_gemm_bf16(const __nv_bfloat16* __restrict__ Ah, const __nv_bfloat16* __restrict__ Al,
                   const __nv_bfloat16* __restrict__ Bh, const __nv_bfloat16* __restrict__ Bl,
                   __half* __restrict__ C16, int M, int N)
{
    extern __shared__ __align__(16) char smem[];
    const uint32_t sb = smem_u32(smem);
    const int tid = threadIdx.x, lane = tid & 31, wid = tid >> 5;
    const int bm = blockIdx.y * 128, bn = blockIdx.x * 128;
    const int wm = (wid >> 2) * 64, wn = (wid & 3) * 32;

    long a_off[2], b_off[2];
    uint32_t a_s[2], b_s[2], b_sz[2];
#pragma unroll
    for (int q = 0; q < 2; q++) {
        int pos = q * 256 + tid;
        int r = pos >> 2, c8 = (pos & 3) * 8;
        a_off[q] = (long)(bm + r) * H_SZ + c8;
        a_s[q] = (uint32_t)(r * 80 + (pos & 3) * 16);
        int gn = bn + r;
        b_sz[q]  = (gn < N) ? 16u : 0u;
        b_off[q] = (long)((gn < N) ? gn : 0) * H_SZ + c8;
        b_s[q] = a_s[q];
    }

    float acc[4][4][4];
#pragma unroll
    for (int m = 0; m < 4; m++)
#pragma unroll
        for (int j = 0; j < 4; j++)
#pragma unroll
            for (int q = 0; q < 4; q++) acc[m][j][q] = 0.f;

#define GB_LOAD(ck, s) do {                                                   \
    const long ko = (long)(ck) * 32;                                          \
    const uint32_t st = sb + (s) * 40960;                                     \
    _Pragma("unroll")                                                         \
    for (int q = 0; q < 2; q++) {                                             \
        cp16(st + a_s[q],         Ah + a_off[q] + ko, 16u);                   \
        cp16(st + 10240 + a_s[q], Al + a_off[q] + ko, 16u);                   \
        cp16(st + 20480 + b_s[q], Bh + b_off[q] + ko, b_sz[q]);               \
        cp16(st + 30720 + b_s[q], Bl + b_off[q] + ko, b_sz[q]);               \
    }                                                                         \
} while (0)

    GB_LOAD(0, 0); CP_COMMIT();
    GB_LOAD(1, 1); CP_COMMIT();

    for (int ck = 0; ck < 32; ck++) {
        const int s = ck & 1;
        CP_WAIT1();
        __syncthreads();
        const uint32_t sA = sb + s * 40960;
        const uint32_t sB = sA + 20480;
#pragma unroll
        for (int ks = 0; ks < 2; ks++) {
            uint32_t ah[4][4], al[4][4], bh[8], bl[8];
            const int arow = lane & 15;
            const uint32_t ac = (uint32_t)(((lane >> 4) * 8 + ks * 16) * 2);
#pragma unroll
            for (int mf = 0; mf < 4; mf++) {
                uint32_t ad = sA + (uint32_t)((wm + mf * 16 + arow) * 80) + ac;
                ldsm4(ah[mf], ad);
                ldsm4(al[mf], ad + 10240);
            }
            const int brow = (lane & 7) + ((lane >> 4) & 1) * 8;
            const uint32_t bcd = (uint32_t)(((((lane >> 3) & 1) * 8) + ks * 16) * 2);
#pragma unroll
            for (int pf = 0; pf < 2; pf++) {
                uint32_t bd = sB + (uint32_t)((wn + pf * 16 + brow) * 80) + bcd;
                ldsm4(&bh[pf * 4], bd);
                ldsm4(&bl[pf * 4], bd + 10240);
            }
#pragma unroll
            for (int m = 0; m < 4; m++)
#pragma unroll
                for (int j = 0; j < 4; j++) {
                    const int bi = (j >> 1) * 4 + (j & 1) * 2;
                    mma_bf16(acc[m][j], ah[m], bh[bi], bh[bi + 1]);
                    mma_bf16(acc[m][j], al[m], bh[bi], bh[bi + 1]);
                    mma_bf16(acc[m][j], ah[m], bl[bi], bl[bi + 1]);
                }
        }
        __syncthreads();
        if (ck + 2 < 32) GB_LOAD(ck + 2, s);
        CP_COMMIT();
    }

#pragma unroll
    for (int m = 0; m < 4; m++) {
        const int r0 = bm + wm + m * 16 + (lane >> 2);
#pragma unroll
        for (int j = 0; j < 4; j++) {
            const int col = bn + wn + j * 8 + (lane & 3) * 2;
#pragma unroll
            for (int hh = 0; hh < 2; hh++) {
                const int r = r0 + hh * 8;
                if (col < N)     C16[(size_t)r * N + col]     = __float2half(acc[m][j][hh * 2 + 0]);
                if (col + 1 < N) C16[(size_t)r * N + col + 1] = __float2half(acc[m][j][hh * 2 + 1]);
            }
        }
    }
#undef GB_LOAD
}

// ===================== fp16 GEMM (128x256), single A-pass ===================
template <bool GATHER>
__global__ __launch_bounds__(256, 1)
void mma_gemm_f16(const __half* __restrict__ Ah,
                  const __half* __restrict__ Bh,
                  const int* __restrict__ gidx, const float* __restrict__ bias,
                  float* __restrict__ C, int M, int N)
{
    extern __shared__ __align__(16) char smem[];
    const uint32_t sb = smem_u32(smem);
    const int tid = threadIdx.x, lane = tid & 31, wid = tid >> 5;
    const int bm = blockIdx.y * 128, bn = blockIdx.x * 256;
    const int wm = (wid >> 2) * 64, wn = (wid & 3) * 64;

    long a_off[2];
    uint32_t a_s[2];
#pragma unroll
    for (int q = 0; q < 2; q++) {
        int pos = q * 256 + tid;
        int r = pos >> 2, c8 = (pos & 3) * 8;
        long ar = GATHER ? (long)gidx[bm + r] : (long)(bm + r);
        a_off[q] = ar * H_SZ + c8;
        a_s[q] = (uint32_t)(r * 80 + (pos & 3) * 16);
    }
    long b_off[4];
    uint32_t b_s[4], b_sz[4];
#pragma unroll
    for (int q = 0; q < 4; q++) {
        int pos = q * 256 + tid;
        int r = pos >> 2, c8 = (pos & 3) * 8;
        int gn = bn + r;
        b_sz[q]  = (gn < N) ? 16u : 0u;
        b_off[q] = (long)((gn < N) ? gn : 0) * H_SZ + c8;
        b_s[q] = (uint32_t)(r * 80 + (pos & 3) * 16);
    }

    float acc[4][8][4];
#pragma unroll
    for (int m = 0; m < 4; m++)
#pragma unroll
        for (int j = 0; j < 8; j++)
#pragma unroll
            for (int q = 0; q < 4; q++) acc[m][j][q] = 0.f;

#define G2_LOAD(ck, s) do {                                                   \
    const long ko = (long)(ck) * 32;                                          \
    const uint32_t st = sb + (s) * 30720;                                     \
    _Pragma("unroll")                                                         \
    for (int q = 0; q < 2; q++)                                               \
        cp16(st + a_s[q], Ah + a_off[q] + ko, 16u);                           \
    _Pragma("unroll")                                                         \
    for (int q = 0; q < 4; q++)                                               \
        cp16(st + 10240 + b_s[q], Bh + b_off[q] + ko, b_sz[q]);               \
} while (0)

    G2_LOAD(0, 0); CP_COMMIT();
    G2_LOAD(1, 1); CP_COMMIT();

    for (int ck = 0; ck < 32; ck++) {
        const int s = ck & 1;
        CP_WAIT1();
        __syncthreads();
        const uint32_t sA = sb + s * 30720;
        const uint32_t sB = sA + 10240;
#pragma unroll
        for (int ks = 0; ks < 2; ks++) {
            uint32_t ah[4][4], bh[16];
            const int arow = lane & 15;
            const uint32_t ac = (uint32_t)(((lane >> 4) * 8 + ks * 16) * 2);
#pragma unroll
            for (int mf = 0; mf < 4; mf++) {
                uint32_t ad = sA + (uint32_t)((wm + mf * 16 + arow) * 80) + ac;
                ldsm4(ah[mf], ad);
            }
            const int brow = (lane & 7) + ((lane >> 4) & 1) * 8;
            const uint32_t bcd = (uint32_t)(((((lane >> 3) & 1) * 8) + ks * 16) * 2);
#pragma unroll
            for (int pf = 0; pf < 4; pf++) {
                uint32_t bd = sB + (uint32_t)((wn + pf * 16 + brow) * 80) + bcd;
                ldsm4(&bh[pf * 4], bd);
            }
#pragma unroll
            for (int m = 0; m < 4; m++)
#pragma unroll
                for (int j = 0; j < 8; j++) {
                    const int bi = (j >> 1) * 4 + (j & 1) * 2;
                    mma_f16(acc[m][j], ah[m], bh[bi], bh[bi + 1]);
                }
        }
        __syncthreads();
        if (ck + 2 < 32) G2_LOAD(ck + 2, s);
        CP_COMMIT();
    }

#pragma unroll
    for (int m = 0; m < 4; m++) {
        const int r0 = bm + wm + m * 16 + (lane >> 2);
#pragma unroll
        for (int j = 0; j < 8; j++) {
            const int col = bn + wn + j * 8 + (lane & 3) * 2;
#pragma unroll
            for (int hh = 0; hh < 2; hh++) {
                const int r = r0 + hh * 8;
                if (col < N)     C[(size_t)r * N + col]     = acc[m][j][hh * 2 + 0] + bias[col];
                if (col + 1 < N) C[(size_t)r * N + col + 1] = acc[m][j][hh * 2 + 1] + bias[col + 1];
            }
        }
    }
#undef G2_LOAD
}

// ===================== persistent LSTM scan ==================================
// ONE kernel runs all 256 timesteps. 128 CTAs (<=148 SMs, all resident),
// grid barrier between steps (atomic counter). Each CTA owns 8 hidden units
// (all 4 gates, M=32) x 64 batch. W_h slice (32x1024 fp16) loaded into SMEM
// ONCE; c lives in registers for the whole kernel.
// SMEM: A persistent 81920 B | B ring 4 x 5120 B (gate-exchange Gs aliases B).
#define SCAN_CTAS 128
#define A_BYTES   (32 * 2560)            // 32 chunks x (32 rows x 80 B)
#define SB_STG    5120                   // 64 rows x 80 B
#define SCAN_SMEM (A_BYTES + 4 * SB_STG) // 102400 B

__global__ __launch_bounds__(128, 1)
void lstm_scan_persistent(const __half* __restrict__ WhT16,
                          const float* __restrict__ px,
                          const float* __restrict__ c_in,
                          __half* __restrict__ res,    // (T+1) slabs of [B,H]
                          float* __restrict__ hf, float* __restrict__ cf)
{
    extern __shared__ __align__(16) char smem[];
    const uint32_t sb = smem_u32(smem);
    const int tid = threadIdx.x, lane = tid & 31, wid = tid >> 5;
    const int u0 = blockIdx.x * 8;
    const int wm = (wid >> 1) * 16, wn = (wid & 1) * 32;

    // ---- load W_h slice into persistent SMEM (once) ----
    for (int idx = tid; idx < 4096; idx += 128) {
        int ck = idx >> 7, pos = idx & 127;
        int r = pos >> 2, seg = pos & 3;
        long grow = (long)(r >> 3) * H_SZ + u0 + (r & 7);   // gate*H + unit
        const __half* src = WhT16 + grow * H_SZ + ck * 32 + seg * 8;
        cp16(sb + (uint32_t)(ck * 2560 + r * 80 + seg * 16), src, 16u);
    }
    CP_COMMIT();

    // ---- c into registers (CTA owns b x (u0..u0+7); thread: 4 b's x 1 u) ----
    const int u = tid & 7;
    const int b0 = (tid >> 3) * 4;
    const int gu = u0 + u;
    float creg[4];
#pragma unroll
    for (int jj = 0; jj < 4; jj++) creg[jj] = c_in[(b0 + jj) * H_SZ + gu];

    // B-operand (h) cp.async descriptors
    uint32_t b_s[2];
    long b_row[2];
#pragma unroll
    for (int q = 0; q < 2; q++) {
        int pos = q * 128 + tid;
        int r = pos >> 2, c8 = (pos & 3) * 8;
        b_row[q] = (long)r * H_SZ + c8;
        b_s[q] = (uint32_t)(r * 80 + (pos & 3) * 16);
    }
    const uint32_t sbB = sb + A_BYTES;
    float* Gs = (float*)(smem + A_BYTES);   // aliases B ring between steps

    CP_WAIT0();
    __syncthreads();   // W_h slice ready

#define SB_LOAD(hhp, ck, s) do {                                              \
    const long ko = (long)(ck) * 32;                                          \
    const uint32_t st = sbB + (s) * SB_STG;                                   \
    _Pragma("unroll")                                                         \
    for (int q = 0; q < 2; q++)                                               \
        cp16(st + b_s[q], (hhp) + b_row[q] + ko, 16u);                        \
} while (0)

    for (int t = 0; t < T_STEPS; t++) {
        const __half* hh = res + (size_t)t * BH;
        __half*       oh = res + (size_t)(t + 1) * BH;
        const float*  px_t = px + (size_t)t * B_SZ * H4;

        // prefetch px gate values early (latency hidden behind K-loop)
        float pr[4][4];
#pragma unroll
        for (int jj = 0; jj < 4; jj++) {
            const float* pxb = px_t + (size_t)(b0 + jj) * H4;
            pr[jj][0] = pxb[gu];
            pr[jj][1] = pxb[1024 + gu];
            pr[jj][2] = pxb[2048 + gu];
            pr[jj][3] = pxb[3072 + gu];
        }

        float acc[4][4];
#pragma unroll
        for (int j = 0; j < 4; j++)
#pragma unroll
            for (int q = 0; q < 4; q++) acc[j][q] = 0.f;

        SB_LOAD(hh, 0, 0); CP_COMMIT();
        SB_LOAD(hh, 1, 1); CP_COMMIT();
        SB_LOAD(hh, 2, 2); CP_COMMIT();

        for (int ck = 0; ck < 32; ck++) {
            const int s = ck & 3;
            CP_WAIT2();
            __syncthreads();
            const uint32_t sA = sb + (uint32_t)(ck * 2560);
            const uint32_t sB = sbB + s * SB_STG;
#pragma unroll
            for (int ks = 0; ks < 2; ks++) {
                uint32_t ah[4], bh[8];
                const uint32_t ac = (uint32_t)(((lane >> 4) * 8 + ks * 16) * 2);
                ldsm4(ah, sA + (uint32_t)((wm + (lane & 15)) * 80) + ac);
                const int brow = (lane & 7) + ((lane >> 4) & 1) * 8;
                const uint32_t bcd = (uint32_t)(((((lane >> 3) & 1) * 8) + ks * 16) * 2);
#pragma unroll
                for (int pf = 0; pf < 2; pf++) {
                    uint32_t bd = sB + (uint32_t)((wn + pf * 16 + brow) * 80) + bcd;
                    ldsm4(&bh[pf * 4], bd);
                }
#pragma unroll
                for (int j = 0; j < 4; j++) {
                    const int bi = (j >> 1) * 4 + (j & 1) * 2;
                    mma_f16(acc[j], ah, bh[bi], bh[bi + 1]);
                }
            }
            if (ck + 3 < 32) { SB_LOAD(hh, ck + 3, (ck + 3) & 3); }
            CP_COMMIT();
        }

        __syncthreads();   // all B reads done; Gs may overwrite B ring
        {
            const int row = wm + (lane >> 2);
#pragma unroll
            for (int j = 0; j < 4; j++) {
                const int col = wn + j * 8 + (lane & 3) * 2;
                Gs[row * 65 + col]           = acc[j][0];
                Gs[row * 65 + col + 1]       = acc[j][1];
                Gs[(row + 8) * 65 + col]     = acc[j][2];
                Gs[(row + 8) * 65 + col + 1] = acc[j][3];
            }
        }
        __syncthreads();

#pragma unroll
        for (int jj = 0; jj < 4; jj++) {
            const int b = b0 + jj;
            float gi = Gs[(0 * 8 + u) * 65 + b] + pr[jj][0];
            float gf = Gs[(1 * 8 + u) * 65 + b] + pr[jj][1];
            float gg = Gs[(2 * 8 + u) * 65 + b] + pr[jj][2];
            float go = Gs[(3 * 8 + u) * 65 + b] + pr[jj][3];
            float si = 1.f / (1.f + expf(-gi));
            float sf = 1.f / (1.f + expf(-gf));
            float so = 1.f / (1.f + expf(-go));
            float tg = tanhf(gg);
            float cn = sf * creg[jj] + si * tg;
            float hn = so * tanhf(cn);
            creg[jj] = cn;
            const int ci = b * H_SZ + gu;
            oh[ci] = __float2half(hn);
            if (t == T_STEPS - 1) { hf[ci] = hn; cf[ci] = cn; }
        }

        // ---- grid barrier (skip after last step) ----
        if (t < T_STEPS - 1) {
            __threadfence();            // h writes visible device-wide
            __syncthreads();            // whole CTA arrived
            if (tid == 0) {
                atomicAdd(&g_bar, 1u);
                const unsigned target = (unsigned)SCAN_CTAS * (unsigned)(t + 1);
                while (atomicAdd(&g_bar, 0u) < target) { }
            }
            __syncthreads();
            __threadfence();            // acquire side
        }
    }
#undef SB_LOAD
}

// ===================== launch ================================================
extern "C" void kernel_launch(void* const* d_in, const int* in_sizes, int n_in,
                              void* d_out, int out_size)
{
    const int*   x      = (const int*)  d_in[0];
    const float* h      = (const float*)d_in[1];
    const float* c      = (const float*)d_in[2];
    const float* emb    = (const float*)d_in[3];
    const float* W_proj = (const float*)d_in[4];
    const float* b_proj = (const float*)d_in[5];
    const float* W_x    = (const float*)d_in[6];
    const float* W_h    = (const float*)d_in[7];
    const float* b_lstm = (const float*)d_in[8];
    const float* W_out  = (const float*)d_in[9];
    const float* b_out  = (const float*)d_in[10];
    float* out = (float*)d_out;

    float *px, *bc;
    unsigned int* bar;
    __nv_bfloat16 *wxth, *wxtl, *wph, *wpl;
    __half *r16h, *e16h, *wht16, *wot16, *wct16;
    cudaGetSymbolAddress((void**)&px,    g_px);
    cudaGetSymbolAddress((void**)&bc,    g_bc);
    cudaGetSymbolAddress((void**)&bar,   g_bar);
    cudaGetSymbolAddress((void**)&r16h,  g_res16h);
    cudaGetSymbolAddress((void**)&e16h,  g_emb16h);
    cudaGetSymbolAddress((void**)&wxth,  g_WxT_hi);
    cudaGetSymbolAddress((void**)&wxtl,  g_WxT_lo);
    cudaGetSymbolAddress((void**)&wht16, g_WhT16);
    cudaGetSymbolAddress((void**)&wot16, g_WoT16);
    cudaGetSymbolAddress((void**)&wph,   g_Wp_hi);
    cudaGetSymbolAddress((void**)&wpl,   g_Wp_lo);
    cudaGetSymbolAddress((void**)&wct16, g_WcT16);

    cudaFuncSetAttribute(mma_gemm_bf16,
                         cudaFuncAttributeMaxDynamicSharedMemorySize, G_SMEM_BYTES);
    cudaFuncSetAttribute(mma_gemm_f16<true>,
                         cudaFuncAttributeMaxDynamicSharedMemorySize, 2 * 30720);
    cudaFuncSetAttribute(mma_gemm_f16<false>,
                         cudaFuncAttributeMaxDynamicSharedMemorySize, 2 * 30720);
    cudaFuncSetAttribute(lstm_scan_persistent,
                         cudaFuncAttributeMaxDynamicSharedMemorySize, SCAN_SMEM);

    // ---------- prepass ----------
    cudaMemsetAsync(bar, 0, sizeof(unsigned int), 0);
    split_kernel<<<512, 256>>>(W_proj, wph, wpl, (long)H_SZ * H_SZ);
    conv16_kernel<<<2048, 256>>>(emb, e16h, (long)O_SZ * H_SZ);
    conv16_kernel<<<64, 256>>>(h, r16h, (long)BH);   // slab 0 = h_{-1}
    transpose_split_kernel<<<dim3(H4 / 32, H_SZ / 32), 256>>>(W_x, wxth, wxtl, H_SZ, H4);
    transpose16_kernel<<<dim3(H4 / 32, H_SZ / 32), 256>>>(W_h, wht16, H_SZ, H4);
    transpose16_kernel<<<dim3((O_SZ + 31) / 32, H_SZ / 32), 256>>>(W_out, wot16, H_SZ, O_SZ);
    bc_kernel<<<(H4 + 255) / 256, 256>>>(b_proj, W_x, b_lstm, bc);

    // ---------- Wc = (W_proj @ W_x)^T  (bf16x3, fp16 out) ----------
    mma_gemm_bf16<<<dim3(H_SZ / 128, H4 / 128), 256, G_SMEM_BYTES>>>(
        wxth, wxtl, wph, wpl, wct16, H4, H_SZ);

    // ---------- px = emb[x] @ WcT^T + bc  (single launch) ----------
    mma_gemm_f16<true><<<dim3(H4 / 256, TB / 128), 256, 2 * 30720>>>(
        e16h, wct16, x, bc, px, TB, H4);

    // ---------- persistent LSTM scan (exclusive occupancy) ----------
    float* hf_out = out + (size_t)TB * O_SZ;
    float* cf_out = hf_out + BH;
    lstm_scan_persistent<<<SCAN_CTAS, 128, SCAN_SMEM>>>(
        wht16, px, c, r16h, hf_out, cf_out);

    // ---------- out = res @ W_out^T + b_out  (single launch) ----------
    mma_gemm_f16<false><<<dim3((O_SZ + 255) / 256, TB / 128), 256, 2 * 30720>>>(
        r16h + BH, wot16, nullptr, b_out, out, TB, O_SZ);
}